// round 12
// baseline (speedup 1.0000x reference)
#include <cuda_runtime.h>
#include <cuda_fp16.h>
#include <cstdint>

#define BB   256
#define TT   2048
#define FIN  9
#define T1   1024
#define TPP  512
#define NN   131072
#define EE   2097152
#define HID  64
#define TW   260
#define PREP_BLOCKS 128

// ---------------- scratch (static device globals; no runtime alloc) ----------
__device__ int      d_cnt[NN];
__device__ int      d_ptr[NN];
__device__ int      d_cur[NN];
__device__ int      d_bsum[PREP_BLOCKS];
__device__ int      d_srow[EE];
__device__ float    d_dinv[NN];
__device__ float    d_h1[(size_t)BB * 16 * T1];   // conv1 output, CHANNEL-MAJOR [b][c][t]
__device__ __align__(16) __half d_g16[(size_t)NN * 32];    // layer-1 gather input (fp16)
__device__ __align__(16) __half d_gB16[(size_t)NN * HID];  // layer-2 gather input (fp16)
__device__ unsigned g_cnt;                        // grid barrier counter (memset per launch)

// ---------------- streams/events for capture fork/join ----------------------
static cudaStream_t g_s2;
static cudaEvent_t  g_ev0, g_evScat;
static void*        g_cnt_addr;
namespace {
struct StreamInit {
    StreamInit() {
        cudaStreamCreateWithFlags(&g_s2, cudaStreamNonBlocking);
        cudaEventCreateWithFlags(&g_ev0,    cudaEventDisableTiming);
        cudaEventCreateWithFlags(&g_evScat, cudaEventDisableTiming);
        cudaGetSymbolAddress(&g_cnt_addr, g_cnt);
    }
} g_streamInit;
}

// ---------------- grid barrier (single-wave, monotonic counter) --------------
__device__ __forceinline__ void gridbar(unsigned& phase) {
    __syncthreads();
    if (threadIdx.x == 0) {
        __threadfence();
        atomicAdd(&g_cnt, 1u);
        unsigned target = (++phase) * gridDim.x;
        while (atomicAdd(&g_cnt, 0u) < target) __nanosleep(64);
        __threadfence();
    }
    __syncthreads();
}

// ---------------- fused graph prep: zero+hist+scan+finalize+scatter ----------
__global__ void __launch_bounds__(1024)
prep_kernel(const int* __restrict__ row, const int* __restrict__ col) {
    __shared__ int s[1024];
    __shared__ int sb[PREP_BLOCKS];
    int tid = threadIdx.x, bid = blockIdx.x;
    int i = bid * 1024 + tid;
    unsigned phase = 0;

    d_cnt[i] = 0;
    gridbar(phase);

    #pragma unroll
    for (int j = 0; j < EE / NN; j++)
        atomicAdd(&d_cnt[col[i + j * NN]], 1);
    gridbar(phase);

    int v = d_cnt[i];
    s[tid] = v;
    __syncthreads();
    #pragma unroll
    for (int off = 1; off < 1024; off <<= 1) {
        int t = (tid >= off) ? s[tid - off] : 0;
        __syncthreads();
        s[tid] += t;
        __syncthreads();
    }
    int le = s[tid] - v;
    if (tid == 1023) d_bsum[bid] = s[1023];
    gridbar(phase);

    if (tid < PREP_BLOCKS) sb[tid] = d_bsum[tid];
    __syncthreads();
    #pragma unroll
    for (int off = 1; off < PREP_BLOCKS; off <<= 1) {
        int t = (tid < PREP_BLOCKS && tid >= off) ? sb[tid - off] : 0;
        __syncthreads();
        if (tid < PREP_BLOCKS) sb[tid] += t;
        __syncthreads();
    }
    int bex = (bid == 0) ? 0 : sb[bid - 1];

    int p = le + bex;
    d_ptr[i] = p;
    d_cur[i] = p;
    d_dinv[i] = rsqrtf((float)v + 1.0f);
    gridbar(phase);

    #pragma unroll
    for (int j = 0; j < EE / NN; j++) {
        int e = i + j * NN;
        int c = col[e];
        int q = atomicAdd(&d_cur[c], 1);
        d_srow[q] = row[e];
    }
}

// ---------------- conv1: (B,T,9) -> relu -> pool2 -> d_h1 [b][c][t] ----------
__global__ void conv1_kernel(const float* __restrict__ x,
                             const float* __restrict__ w,
                             const float* __restrict__ bias) {
    __shared__ __align__(16) float xs[TW * 9];
    __shared__ __align__(16) float ws[720];
    __shared__ float bs[16];
    int b = blockIdx.y, tp0 = blockIdx.x * 128, tid = threadIdx.x;

    for (int j = tid; j < 720; j += 128) {
        int c = j & 15, r = j >> 4, f = r / 5, k = r - f * 5;
        ws[j] = w[c * 45 + f * 5 + k];
    }
    if (tid < 16) bs[tid] = bias[tid];

    int base = 2 * tp0 - 2;
    const float* xb = x + (size_t)b * TT * FIN;
    for (int j = tid; j < TW * 9; j += 128) {
        int t = base + j / 9, f = j - (j / 9) * 9;
        xs[j] = (t >= 0 && t < TT) ? xb[t * 9 + f] : 0.0f;
    }
    __syncthreads();

    float s0[16], s1[16];
    #pragma unroll
    for (int c = 0; c < 16; c++) { s0[c] = 0.f; s1[c] = 0.f; }

    #pragma unroll
    for (int f = 0; f < 9; f++) {
        float v[6];
        #pragma unroll
        for (int j = 0; j < 6; j++) v[j] = xs[(2 * tid + j) * 9 + f];
        #pragma unroll
        for (int k = 0; k < 5; k++) {
            const float4* wr = (const float4*)&ws[(f * 5 + k) * 16];
            float a = v[k], bb = v[k + 1];
            #pragma unroll
            for (int q = 0; q < 4; q++) {
                float4 w4 = wr[q];
                s0[q*4+0] += w4.x * a;  s1[q*4+0] += w4.x * bb;
                s0[q*4+1] += w4.y * a;  s1[q*4+1] += w4.y * bb;
                s0[q*4+2] += w4.z * a;  s1[q*4+2] += w4.z * bb;
                s0[q*4+3] += w4.w * a;  s1[q*4+3] += w4.w * bb;
            }
        }
    }

    float* hb = d_h1 + (size_t)b * 16 * T1 + tp0 + tid;
    #pragma unroll
    for (int c = 0; c < 16; c++)
        hb[c * T1] = fmaxf(fmaxf(s0[c], s1[c]) + bs[c], 0.f);
}

// ------- conv2 (register-blocked): d_h1 [b][c][t] -> g16 = fp16(dinv*h2) ----
__global__ void conv2_kernel(const float* __restrict__ w2,
                             const float* __restrict__ b2) {
    __shared__ __align__(16) float buf[16 * TW];
    __shared__ __align__(16) float ws[2560];
    __shared__ float bs[32];
    int b = blockIdx.y, tid = threadIdx.x;
    int cg = tid & 7, pg = tid >> 3;
    int t0 = blockIdx.x * 256;

    for (int j = tid; j < 2560; j += 128) {
        int c = j & 31, r = j >> 5;
        ws[j] = w2[c * 80 + r];
    }
    if (tid < 32) bs[tid] = b2[tid];

    int base = t0 - 2;
    const float* hb = d_h1 + (size_t)b * 16 * T1;
    #pragma unroll
    for (int ci = 0; ci < 16; ci++)
        for (int j = tid; j < TW; j += 128) {
            int t = base + j;
            buf[ci * TW + j] = (t >= 0 && t < T1) ? hb[ci * T1 + t] : 0.f;
        }
    __syncthreads();

    float acc[64];
    #pragma unroll
    for (int o = 0; o < 64; o++) acc[o] = 0.f;

    #pragma unroll 2
    for (int ci = 0; ci < 16; ci++) {
        float v[20];
        const float4* vp = (const float4*)(buf + ci * TW + pg * 16);
        #pragma unroll
        for (int q = 0; q < 5; q++) {
            float4 t4 = vp[q];
            v[q*4+0] = t4.x; v[q*4+1] = t4.y; v[q*4+2] = t4.z; v[q*4+3] = t4.w;
        }
        #pragma unroll
        for (int k = 0; k < 5; k++) {
            float4 w4 = *(const float4*)&ws[(ci * 5 + k) * 32 + cg * 4];
            #pragma unroll
            for (int p = 0; p < 16; p++) {
                float a = v[p + k];
                acc[p*4+0] += a * w4.x;
                acc[p*4+1] += a * w4.y;
                acc[p*4+2] += a * w4.z;
                acc[p*4+3] += a * w4.w;
            }
        }
    }

    int nbase = b * TPP + (t0 >> 1) + pg * 8;
    #pragma unroll
    for (int pp = 0; pp < 8; pp++) {
        int n = nbase + pp;
        float dv = d_dinv[n];
        int pa = pp * 2 * 4, pb = pa + 4;
        float c0 = fmaxf(fmaxf(acc[pa+0], acc[pb+0]) + bs[cg*4+0], 0.f) * dv;
        float c1 = fmaxf(fmaxf(acc[pa+1], acc[pb+1]) + bs[cg*4+1], 0.f) * dv;
        float c2 = fmaxf(fmaxf(acc[pa+2], acc[pb+2]) + bs[cg*4+2], 0.f) * dv;
        float c3 = fmaxf(fmaxf(acc[pa+3], acc[pb+3]) + bs[cg*4+3], 0.f) * dv;
        __half2* o = (__half2*)(d_g16 + (size_t)n * 32 + cg * 4);
        o[0] = __floats2half2_rn(c0, c1);
        o[1] = __floats2half2_rn(c2, c3);
    }
}

// ------- fused layer 1: 2 nodes/warp (half-warp each) + GEMM 32->64 ---------
__global__ void gcn1_fused_kernel(const float* __restrict__ w,
                                  const float* __restrict__ bias) {
    __shared__ __align__(16) float ws[2048];     // W1 [c][o], 32x64
    __shared__ float bs[64];
    __shared__ float st[8][64];                  // per-warp: 2 nodes x 32 ch
    int tid = threadIdx.x;
    for (int j = tid; j < 2048; j += 256) ws[j] = w[j];
    if (tid < 64) bs[tid] = bias[tid];
    __syncthreads();

    int warp = tid >> 5, lane = tid & 31;
    int half = lane >> 4, hl = lane & 15;
    int nbase = (blockIdx.x * 8 + warp) * 2;
    int n = nbase + half;
    int p = d_ptr[n];
    int cnt = d_cnt[n];
    const __half2* gp = (const __half2*)d_g16 + hl;   // +r*16 selects row r

    float2 acc = __half22float2(gp[n << 4]);          // self loop

    int e = 0;
    for (; e + 8 <= cnt; e += 8) {
        int r0 = d_srow[p+e],   r1 = d_srow[p+e+1], r2 = d_srow[p+e+2], r3 = d_srow[p+e+3];
        int r4 = d_srow[p+e+4], r5 = d_srow[p+e+5], r6 = d_srow[p+e+6], r7 = d_srow[p+e+7];
        float2 v0 = __half22float2(gp[r0 << 4]);
        float2 v1 = __half22float2(gp[r1 << 4]);
        float2 v2 = __half22float2(gp[r2 << 4]);
        float2 v3 = __half22float2(gp[r3 << 4]);
        float2 v4 = __half22float2(gp[r4 << 4]);
        float2 v5 = __half22float2(gp[r5 << 4]);
        float2 v6 = __half22float2(gp[r6 << 4]);
        float2 v7 = __half22float2(gp[r7 << 4]);
        acc.x += ((v0.x + v1.x) + (v2.x + v3.x)) + ((v4.x + v5.x) + (v6.x + v7.x));
        acc.y += ((v0.y + v1.y) + (v2.y + v3.y)) + ((v4.y + v5.y) + (v6.y + v7.y));
    }
    for (; e < cnt; e++) {
        int r = d_srow[p + e];
        float2 v = __half22float2(gp[r << 4]);
        acc.x += v.x; acc.y += v.y;
    }

    st[warp][half * 32 + 2 * hl]     = acc.x;
    st[warp][half * 32 + 2 * hl + 1] = acc.y;
    __syncwarp();

    #pragma unroll
    for (int k = 0; k < 2; k++) {
        int nk = nbase + k;
        float s0 = 0.f, s1 = 0.f;
        #pragma unroll
        for (int c = 0; c < 32; c++) {
            float v = st[warp][k * 32 + c];
            float2 wp = ((const float2*)&ws[c * 64])[lane];
            s0 += v * wp.x;
            s1 += v * wp.y;
        }
        float dv = d_dinv[nk];
        float o0 = fmaxf(dv * s0 + bs[2 * lane],     0.f) * dv;
        float o1 = fmaxf(dv * s1 + bs[2 * lane + 1], 0.f) * dv;
        ((__half2*)d_gB16)[(nk << 5) + lane] = __floats2half2_rn(o0, o1);
    }
}

// ---------------- init out = fcb (per replay, before atomics) ----------------
__global__ void init_out_kernel(const float* __restrict__ fcb, float* __restrict__ out) {
    out[blockIdx.x * 6 + threadIdx.x] = fcb[threadIdx.x];
}

// ------- fused layer 2 + pool + FC: 2 nodes/warp gather + GEMM + pooled FC --
// Block = 16 consecutive nodes (all in batch b = blockIdx.x >> 5).
__global__ void gcn2_pool_kernel(const float* __restrict__ w,
                                 const float* __restrict__ bias,
                                 const float* __restrict__ fcw,
                                 float* __restrict__ out) {
    __shared__ __align__(16) float ws[4096];     // W2 [c][o], 64x64
    __shared__ float bs[64];
    __shared__ float fw[384];                    // fcW [o][k], 6x64
    __shared__ __align__(16) float st[8][128];   // per-warp: 2 nodes x 64 ch
    __shared__ float po[6];                      // block-level pooled partials
    int tid = threadIdx.x;
    for (int j = tid; j < 4096; j += 256) ws[j] = w[j];
    if (tid < 64) bs[tid] = bias[tid];
    else if (tid >= 64 && tid < 70) po[tid - 64] = 0.f;
    for (int j = tid; j < 384; j += 256) fw[j] = fcw[j];
    __syncthreads();

    int warp = tid >> 5, lane = tid & 31;
    int half = lane >> 4, hl = lane & 15;
    int nbase = blockIdx.x * 16 + warp * 2;
    int n = nbase + half;
    int p = d_ptr[n];
    int cnt = d_cnt[n];
    const uint2* gp = (const uint2*)d_gB16 + hl;  // +r*16 selects row r (128B rows)

    // self loop (lane covers channels 4*hl .. 4*hl+3)
    float a0, a1, a2, a3;
    {
        uint2 v = gp[n << 4];
        float2 fa = __half22float2(*(const __half2*)&v.x);
        float2 fb = __half22float2(*(const __half2*)&v.y);
        a0 = fa.x; a1 = fa.y; a2 = fb.x; a3 = fb.y;
    }

    int e = 0;
    for (; e + 4 <= cnt; e += 4) {
        int r0 = d_srow[p+e], r1 = d_srow[p+e+1], r2 = d_srow[p+e+2], r3 = d_srow[p+e+3];
        uint2 v0 = gp[r0 << 4];
        uint2 v1 = gp[r1 << 4];
        uint2 v2 = gp[r2 << 4];
        uint2 v3 = gp[r3 << 4];
        float2 f0a = __half22float2(*(const __half2*)&v0.x), f0b = __half22float2(*(const __half2*)&v0.y);
        float2 f1a = __half22float2(*(const __half2*)&v1.x), f1b = __half22float2(*(const __half2*)&v1.y);
        float2 f2a = __half22float2(*(const __half2*)&v2.x), f2b = __half22float2(*(const __half2*)&v2.y);
        float2 f3a = __half22float2(*(const __half2*)&v3.x), f3b = __half22float2(*(const __half2*)&v3.y);
        a0 += (f0a.x + f1a.x) + (f2a.x + f3a.x);
        a1 += (f0a.y + f1a.y) + (f2a.y + f3a.y);
        a2 += (f0b.x + f1b.x) + (f2b.x + f3b.x);
        a3 += (f0b.y + f1b.y) + (f2b.y + f3b.y);
    }
    for (; e < cnt; e++) {
        int r = d_srow[p + e];
        uint2 v = gp[r << 4];
        float2 fa = __half22float2(*(const __half2*)&v.x);
        float2 fb = __half22float2(*(const __half2*)&v.y);
        a0 += fa.x; a1 += fa.y; a2 += fb.x; a3 += fb.y;
    }

    // stage: st[warp][half*64 + 4*hl + 0..3], 16B-aligned -> STS.128
    *(float4*)&st[warp][half * 64 + 4 * hl] = make_float4(a0, a1, a2, a3);
    __syncwarp();

    // epilogue for both nodes: GEMM 64->64, relu, then pooled-FC contribution
    #pragma unroll
    for (int k = 0; k < 2; k++) {
        int nk = nbase + k;
        float s0 = 0.f, s1 = 0.f;
        #pragma unroll
        for (int c = 0; c < 64; c++) {
            float v = st[warp][k * 64 + c];
            float2 wp = ((const float2*)&ws[c * 64])[lane];
            s0 += v * wp.x;
            s1 += v * wp.y;
        }
        float dv = d_dinv[nk];
        float h0 = fmaxf(dv * s0 + bs[2 * lane],     0.f);   // channel 2*lane
        float h1 = fmaxf(dv * s1 + bs[2 * lane + 1], 0.f);   // channel 2*lane+1

        // FC partials: contrib[o] = sum_lanes h0*fw[o][2l] + h1*fw[o][2l+1]
        #pragma unroll
        for (int o = 0; o < 6; o++) {
            float c6 = h0 * fw[o * 64 + 2 * lane] + h1 * fw[o * 64 + 2 * lane + 1];
            c6 += __shfl_xor_sync(0xffffffffu, c6, 1);
            c6 += __shfl_xor_sync(0xffffffffu, c6, 2);
            c6 += __shfl_xor_sync(0xffffffffu, c6, 4);
            c6 += __shfl_xor_sync(0xffffffffu, c6, 8);
            c6 += __shfl_xor_sync(0xffffffffu, c6, 16);
            if (lane == 0) atomicAdd(&po[o], c6);
        }
    }

    __syncthreads();
    if (tid < 6)
        atomicAdd(&out[(blockIdx.x >> 5) * 6 + tid], po[tid] * (1.0f / TPP));
}

// ---------------- launch -----------------------------------------------------
extern "C" void kernel_launch(void* const* d_in, const int* in_sizes, int n_in,
                              void* d_out, int out_size) {
    const float* x   = (const float*)d_in[0];
    const int*   ei  = (const int*)  d_in[1];
    const float* w1  = (const float*)d_in[2];
    const float* b1  = (const float*)d_in[3];
    const float* w2  = (const float*)d_in[4];
    const float* b2  = (const float*)d_in[5];
    const float* g1w = (const float*)d_in[6];
    const float* g1b = (const float*)d_in[7];
    const float* g2w = (const float*)d_in[8];
    const float* g2b = (const float*)d_in[9];
    const float* fcw = (const float*)d_in[10];
    const float* fcb = (const float*)d_in[11];
    float* out = (float*)d_out;

    // fork: single fused prep kernel on side stream
    cudaEventRecord(g_ev0, 0);
    cudaStreamWaitEvent(g_s2, g_ev0, 0);
    cudaMemsetAsync(g_cnt_addr, 0, sizeof(unsigned), g_s2);
    prep_kernel<<<PREP_BLOCKS, 1024, 0, g_s2>>>(ei, ei + EE);
    cudaEventRecord(g_evScat, g_s2);

    // main stream: conv1 overlaps prep; init out (tiny) too
    conv1_kernel<<<dim3(8, BB), 128>>>(x, w1, b1);
    init_out_kernel<<<BB, 6>>>(fcb, out);
    cudaStreamWaitEvent(0, g_evScat, 0);          // conv2 needs dinv; gathers need CSR
    conv2_kernel<<<dim3(4, BB), 128>>>(w2, b2);

    // fused GCN layers
    gcn1_fused_kernel<<<NN / 16, 256>>>(g1w, g1b);       // 2 nodes/warp
    gcn2_pool_kernel<<<NN / 16, 256>>>(g2w, g2b, fcw, out);  // 2 nodes/warp + pooled FC
}

// round 13
// speedup vs baseline: 1.1578x; 1.1578x over previous
#include <cuda_runtime.h>
#include <cuda_fp16.h>
#include <cstdint>

#define BB   256
#define TT   2048
#define FIN  9
#define T1   1024
#define TPP  512
#define NN   131072
#define EE   2097152
#define HID  64
#define TW   260
#define PREP_BLOCKS 128

// ---------------- scratch (static device globals; no runtime alloc) ----------
__device__ int      d_cnt[NN];
__device__ int      d_ptr[NN];
__device__ int      d_cur[NN];
__device__ int      d_bsum[PREP_BLOCKS];
__device__ int      d_srow[EE];
__device__ float    d_dinv[NN];
__device__ float    d_h1[(size_t)BB * 16 * T1];   // conv1 output, CHANNEL-MAJOR [b][c][t]
__device__ __align__(16) __half d_g16[(size_t)NN * 32];    // layer-1 gather input (fp16)
__device__ __align__(16) __half d_gB16[(size_t)NN * HID];  // layer-2 gather input (fp16)
__device__ unsigned g_cnt;                        // grid barrier counter (memset per launch)

// ---------------- streams/events for capture fork/join ----------------------
static cudaStream_t g_s2;
static cudaEvent_t  g_ev0, g_evScat;
static void*        g_cnt_addr;
namespace {
struct StreamInit {
    StreamInit() {
        cudaStreamCreateWithFlags(&g_s2, cudaStreamNonBlocking);
        cudaEventCreateWithFlags(&g_ev0,    cudaEventDisableTiming);
        cudaEventCreateWithFlags(&g_evScat, cudaEventDisableTiming);
        cudaGetSymbolAddress(&g_cnt_addr, g_cnt);
    }
} g_streamInit;
}

// ---------------- grid barrier (single-wave, monotonic counter) --------------
__device__ __forceinline__ void gridbar(unsigned& phase) {
    __syncthreads();
    if (threadIdx.x == 0) {
        __threadfence();
        atomicAdd(&g_cnt, 1u);
        unsigned target = (++phase) * gridDim.x;
        while (atomicAdd(&g_cnt, 0u) < target) __nanosleep(64);
        __threadfence();
    }
    __syncthreads();
}

// ---------------- fused graph prep: zero+hist+scan+finalize+scatter ----------
__global__ void __launch_bounds__(1024)
prep_kernel(const int* __restrict__ row, const int* __restrict__ col) {
    __shared__ int s[1024];
    __shared__ int sb[PREP_BLOCKS];
    int tid = threadIdx.x, bid = blockIdx.x;
    int i = bid * 1024 + tid;
    unsigned phase = 0;

    d_cnt[i] = 0;
    gridbar(phase);

    #pragma unroll
    for (int j = 0; j < EE / NN; j++)
        atomicAdd(&d_cnt[col[i + j * NN]], 1);
    gridbar(phase);

    int v = d_cnt[i];
    s[tid] = v;
    __syncthreads();
    #pragma unroll
    for (int off = 1; off < 1024; off <<= 1) {
        int t = (tid >= off) ? s[tid - off] : 0;
        __syncthreads();
        s[tid] += t;
        __syncthreads();
    }
    int le = s[tid] - v;
    if (tid == 1023) d_bsum[bid] = s[1023];
    gridbar(phase);

    if (tid < PREP_BLOCKS) sb[tid] = d_bsum[tid];
    __syncthreads();
    #pragma unroll
    for (int off = 1; off < PREP_BLOCKS; off <<= 1) {
        int t = (tid < PREP_BLOCKS && tid >= off) ? sb[tid - off] : 0;
        __syncthreads();
        if (tid < PREP_BLOCKS) sb[tid] += t;
        __syncthreads();
    }
    int bex = (bid == 0) ? 0 : sb[bid - 1];

    int p = le + bex;
    d_ptr[i] = p;
    d_cur[i] = p;
    d_dinv[i] = rsqrtf((float)v + 1.0f);
    gridbar(phase);

    #pragma unroll
    for (int j = 0; j < EE / NN; j++) {
        int e = i + j * NN;
        int c = col[e];
        int q = atomicAdd(&d_cur[c], 1);
        d_srow[q] = row[e];
    }
}

// ---------------- conv1: (B,T,9) -> relu -> pool2 -> d_h1 [b][c][t] ----------
__global__ void conv1_kernel(const float* __restrict__ x,
                             const float* __restrict__ w,
                             const float* __restrict__ bias) {
    __shared__ __align__(16) float xs[TW * 9];
    __shared__ __align__(16) float ws[720];
    __shared__ float bs[16];
    int b = blockIdx.y, tp0 = blockIdx.x * 128, tid = threadIdx.x;

    for (int j = tid; j < 720; j += 128) {
        int c = j & 15, r = j >> 4, f = r / 5, k = r - f * 5;
        ws[j] = w[c * 45 + f * 5 + k];
    }
    if (tid < 16) bs[tid] = bias[tid];

    int base = 2 * tp0 - 2;
    const float* xb = x + (size_t)b * TT * FIN;
    for (int j = tid; j < TW * 9; j += 128) {
        int t = base + j / 9, f = j - (j / 9) * 9;
        xs[j] = (t >= 0 && t < TT) ? xb[t * 9 + f] : 0.0f;
    }
    __syncthreads();

    float s0[16], s1[16];
    #pragma unroll
    for (int c = 0; c < 16; c++) { s0[c] = 0.f; s1[c] = 0.f; }

    #pragma unroll
    for (int f = 0; f < 9; f++) {
        float v[6];
        #pragma unroll
        for (int j = 0; j < 6; j++) v[j] = xs[(2 * tid + j) * 9 + f];
        #pragma unroll
        for (int k = 0; k < 5; k++) {
            const float4* wr = (const float4*)&ws[(f * 5 + k) * 16];
            float a = v[k], bb = v[k + 1];
            #pragma unroll
            for (int q = 0; q < 4; q++) {
                float4 w4 = wr[q];
                s0[q*4+0] += w4.x * a;  s1[q*4+0] += w4.x * bb;
                s0[q*4+1] += w4.y * a;  s1[q*4+1] += w4.y * bb;
                s0[q*4+2] += w4.z * a;  s1[q*4+2] += w4.z * bb;
                s0[q*4+3] += w4.w * a;  s1[q*4+3] += w4.w * bb;
            }
        }
    }

    float* hb = d_h1 + (size_t)b * 16 * T1 + tp0 + tid;
    #pragma unroll
    for (int c = 0; c < 16; c++)
        hb[c * T1] = fmaxf(fmaxf(s0[c], s1[c]) + bs[c], 0.f);
}

// ------- conv2 (8pos x 4ch tile): d_h1 [b][c][t] -> g16 = fp16(dinv*h2) -----
// 256 threads = 32 pos-groups x 8 ch-groups; block covers 256 conv positions.
__global__ void __launch_bounds__(256)
conv2_kernel(const float* __restrict__ w2, const float* __restrict__ b2) {
    __shared__ __align__(16) float buf[16 * TW];
    __shared__ __align__(16) float ws[2560];        // [(ci*5+k)*32 + c]
    __shared__ float bs[32];
    int b = blockIdx.y, tid = threadIdx.x;
    int cg = tid & 7, pg = tid >> 3;                // 8 ch-groups x 32 pos-groups
    int t0 = blockIdx.x * 256;

    for (int j = tid; j < 2560; j += 256) {
        int c = j & 31, r = j >> 5;
        ws[j] = w2[c * 80 + r];
    }
    if (tid < 32) bs[tid] = b2[tid];

    int base = t0 - 2;
    const float* hb = d_h1 + (size_t)b * 16 * T1;
    #pragma unroll
    for (int ci = 0; ci < 16; ci++)
        for (int j = tid; j < TW; j += 256) {
            int t = base + j;
            buf[ci * TW + j] = (t >= 0 && t < T1) ? hb[ci * T1 + t] : 0.f;
        }
    __syncthreads();

    float acc[32];                                  // [p 0..7][cc 0..3]
    #pragma unroll
    for (int o = 0; o < 32; o++) acc[o] = 0.f;

    #pragma unroll 4
    for (int ci = 0; ci < 16; ci++) {
        float v[12];
        const float4* vp = (const float4*)(buf + ci * TW + pg * 8);
        #pragma unroll
        for (int q = 0; q < 3; q++) {
            float4 t4 = vp[q];
            v[q*4+0] = t4.x; v[q*4+1] = t4.y; v[q*4+2] = t4.z; v[q*4+3] = t4.w;
        }
        #pragma unroll
        for (int k = 0; k < 5; k++) {
            float4 w4 = *(const float4*)&ws[(ci * 5 + k) * 32 + cg * 4];
            #pragma unroll
            for (int p = 0; p < 8; p++) {
                float a = v[p + k];
                acc[p*4+0] += a * w4.x;
                acc[p*4+1] += a * w4.y;
                acc[p*4+2] += a * w4.z;
                acc[p*4+3] += a * w4.w;
            }
        }
    }

    // relu + maxpool2 + dinv scale + fp16 store: 4 pooled outputs x 4 channels
    int nbase = b * TPP + (t0 >> 1) + pg * 4;
    #pragma unroll
    for (int pp = 0; pp < 4; pp++) {
        int n = nbase + pp;
        float dv = d_dinv[n];
        int pa = pp * 8, pb = pa + 4;
        float c0 = fmaxf(fmaxf(acc[pa+0], acc[pb+0]) + bs[cg*4+0], 0.f) * dv;
        float c1 = fmaxf(fmaxf(acc[pa+1], acc[pb+1]) + bs[cg*4+1], 0.f) * dv;
        float c2 = fmaxf(fmaxf(acc[pa+2], acc[pb+2]) + bs[cg*4+2], 0.f) * dv;
        float c3 = fmaxf(fmaxf(acc[pa+3], acc[pb+3]) + bs[cg*4+3], 0.f) * dv;
        __half2* o = (__half2*)(d_g16 + (size_t)n * 32 + cg * 4);
        o[0] = __floats2half2_rn(c0, c1);
        o[1] = __floats2half2_rn(c2, c3);
    }
}

// ------- fused layer 1: 2 nodes/warp (half-warp each) + GEMM 32->64 ---------
__global__ void gcn1_fused_kernel(const float* __restrict__ w,
                                  const float* __restrict__ bias) {
    __shared__ __align__(16) float ws[2048];     // W1 [c][o], 32x64
    __shared__ float bs[64];
    __shared__ float st[8][64];                  // per-warp: 2 nodes x 32 ch
    int tid = threadIdx.x;
    for (int j = tid; j < 2048; j += 256) ws[j] = w[j];
    if (tid < 64) bs[tid] = bias[tid];
    __syncthreads();

    int warp = tid >> 5, lane = tid & 31;
    int half = lane >> 4, hl = lane & 15;
    int nbase = (blockIdx.x * 8 + warp) * 2;
    int n = nbase + half;
    int p = d_ptr[n];
    int cnt = d_cnt[n];
    const __half2* gp = (const __half2*)d_g16 + hl;   // +r*16 selects row r

    float2 acc = __half22float2(gp[n << 4]);          // self loop

    int e = 0;
    for (; e + 8 <= cnt; e += 8) {
        int r0 = d_srow[p+e],   r1 = d_srow[p+e+1], r2 = d_srow[p+e+2], r3 = d_srow[p+e+3];
        int r4 = d_srow[p+e+4], r5 = d_srow[p+e+5], r6 = d_srow[p+e+6], r7 = d_srow[p+e+7];
        float2 v0 = __half22float2(gp[r0 << 4]);
        float2 v1 = __half22float2(gp[r1 << 4]);
        float2 v2 = __half22float2(gp[r2 << 4]);
        float2 v3 = __half22float2(gp[r3 << 4]);
        float2 v4 = __half22float2(gp[r4 << 4]);
        float2 v5 = __half22float2(gp[r5 << 4]);
        float2 v6 = __half22float2(gp[r6 << 4]);
        float2 v7 = __half22float2(gp[r7 << 4]);
        acc.x += ((v0.x + v1.x) + (v2.x + v3.x)) + ((v4.x + v5.x) + (v6.x + v7.x));
        acc.y += ((v0.y + v1.y) + (v2.y + v3.y)) + ((v4.y + v5.y) + (v6.y + v7.y));
    }
    for (; e < cnt; e++) {
        int r = d_srow[p + e];
        float2 v = __half22float2(gp[r << 4]);
        acc.x += v.x; acc.y += v.y;
    }

    st[warp][half * 32 + 2 * hl]     = acc.x;
    st[warp][half * 32 + 2 * hl + 1] = acc.y;
    __syncwarp();

    #pragma unroll
    for (int k = 0; k < 2; k++) {
        int nk = nbase + k;
        float s0 = 0.f, s1 = 0.f;
        #pragma unroll
        for (int c = 0; c < 32; c++) {
            float v = st[warp][k * 32 + c];
            float2 wp = ((const float2*)&ws[c * 64])[lane];
            s0 += v * wp.x;
            s1 += v * wp.y;
        }
        float dv = d_dinv[nk];
        float o0 = fmaxf(dv * s0 + bs[2 * lane],     0.f) * dv;
        float o1 = fmaxf(dv * s1 + bs[2 * lane + 1], 0.f) * dv;
        ((__half2*)d_gB16)[(nk << 5) + lane] = __floats2half2_rn(o0, o1);
    }
}

// ---------------- init out = fcb (per replay, before atomics) ----------------
__global__ void init_out_kernel(const float* __restrict__ fcb, float* __restrict__ out) {
    out[blockIdx.x * 6 + threadIdx.x] = fcb[threadIdx.x];
}

// ------- fused layer 2 + pool + FC: 2 nodes/warp gather + GEMM + pooled FC --
// Block = 16 consecutive nodes (all in batch b = blockIdx.x >> 5).
__global__ void gcn2_pool_kernel(const float* __restrict__ w,
                                 const float* __restrict__ bias,
                                 const float* __restrict__ fcw,
                                 float* __restrict__ out) {
    __shared__ __align__(16) float ws[4096];     // W2 [c][o], 64x64
    __shared__ float bs[64];
    __shared__ float fw[384];                    // fcW [o][k], 6x64
    __shared__ __align__(16) float st[8][128];   // per-warp: 2 nodes x 64 ch
    __shared__ float po[6];                      // block-level pooled partials
    int tid = threadIdx.x;
    for (int j = tid; j < 4096; j += 256) ws[j] = w[j];
    if (tid < 64) bs[tid] = bias[tid];
    else if (tid >= 64 && tid < 70) po[tid - 64] = 0.f;
    for (int j = tid; j < 384; j += 256) fw[j] = fcw[j];
    __syncthreads();

    int warp = tid >> 5, lane = tid & 31;
    int half = lane >> 4, hl = lane & 15;
    int nbase = blockIdx.x * 16 + warp * 2;
    int n = nbase + half;
    int p = d_ptr[n];
    int cnt = d_cnt[n];
    const uint2* gp = (const uint2*)d_gB16 + hl;  // +r*16 selects row r (128B rows)

    // self loop (lane covers channels 4*hl .. 4*hl+3)
    float a0, a1, a2, a3;
    {
        uint2 v = gp[n << 4];
        float2 fa = __half22float2(*(const __half2*)&v.x);
        float2 fb = __half22float2(*(const __half2*)&v.y);
        a0 = fa.x; a1 = fa.y; a2 = fb.x; a3 = fb.y;
    }

    int e = 0;
    for (; e + 4 <= cnt; e += 4) {
        int r0 = d_srow[p+e], r1 = d_srow[p+e+1], r2 = d_srow[p+e+2], r3 = d_srow[p+e+3];
        uint2 v0 = gp[r0 << 4];
        uint2 v1 = gp[r1 << 4];
        uint2 v2 = gp[r2 << 4];
        uint2 v3 = gp[r3 << 4];
        float2 f0a = __half22float2(*(const __half2*)&v0.x), f0b = __half22float2(*(const __half2*)&v0.y);
        float2 f1a = __half22float2(*(const __half2*)&v1.x), f1b = __half22float2(*(const __half2*)&v1.y);
        float2 f2a = __half22float2(*(const __half2*)&v2.x), f2b = __half22float2(*(const __half2*)&v2.y);
        float2 f3a = __half22float2(*(const __half2*)&v3.x), f3b = __half22float2(*(const __half2*)&v3.y);
        a0 += (f0a.x + f1a.x) + (f2a.x + f3a.x);
        a1 += (f0a.y + f1a.y) + (f2a.y + f3a.y);
        a2 += (f0b.x + f1b.x) + (f2b.x + f3b.x);
        a3 += (f0b.y + f1b.y) + (f2b.y + f3b.y);
    }
    for (; e < cnt; e++) {
        int r = d_srow[p + e];
        uint2 v = gp[r << 4];
        float2 fa = __half22float2(*(const __half2*)&v.x);
        float2 fb = __half22float2(*(const __half2*)&v.y);
        a0 += fa.x; a1 += fa.y; a2 += fb.x; a3 += fb.y;
    }

    *(float4*)&st[warp][half * 64 + 4 * hl] = make_float4(a0, a1, a2, a3);
    __syncwarp();

    // epilogue: GEMM 64->64 + relu for both nodes; FC partials accumulated
    // across both nodes, single butterfly reduce at the end.
    float f6[6];
    #pragma unroll
    for (int o = 0; o < 6; o++) f6[o] = 0.f;

    #pragma unroll
    for (int k = 0; k < 2; k++) {
        int nk = nbase + k;
        float s0 = 0.f, s1 = 0.f;
        #pragma unroll
        for (int c = 0; c < 64; c++) {
            float v = st[warp][k * 64 + c];
            float2 wp = ((const float2*)&ws[c * 64])[lane];
            s0 += v * wp.x;
            s1 += v * wp.y;
        }
        float dv = d_dinv[nk];
        float h0 = fmaxf(dv * s0 + bs[2 * lane],     0.f);
        float h1 = fmaxf(dv * s1 + bs[2 * lane + 1], 0.f);

        #pragma unroll
        for (int o = 0; o < 6; o++)
            f6[o] += h0 * fw[o * 64 + 2 * lane] + h1 * fw[o * 64 + 2 * lane + 1];
    }

    #pragma unroll
    for (int o = 0; o < 6; o++) {
        float c6 = f6[o];
        c6 += __shfl_xor_sync(0xffffffffu, c6, 1);
        c6 += __shfl_xor_sync(0xffffffffu, c6, 2);
        c6 += __shfl_xor_sync(0xffffffffu, c6, 4);
        c6 += __shfl_xor_sync(0xffffffffu, c6, 8);
        c6 += __shfl_xor_sync(0xffffffffu, c6, 16);
        if (lane == 0) atomicAdd(&po[o], c6);
    }

    __syncthreads();
    if (tid < 6)
        atomicAdd(&out[(blockIdx.x >> 5) * 6 + tid], po[tid] * (1.0f / TPP));
}

// ---------------- launch -----------------------------------------------------
extern "C" void kernel_launch(void* const* d_in, const int* in_sizes, int n_in,
                              void* d_out, int out_size) {
    const float* x   = (const float*)d_in[0];
    const int*   ei  = (const int*)  d_in[1];
    const float* w1  = (const float*)d_in[2];
    const float* b1  = (const float*)d_in[3];
    const float* w2  = (const float*)d_in[4];
    const float* b2  = (const float*)d_in[5];
    const float* g1w = (const float*)d_in[6];
    const float* g1b = (const float*)d_in[7];
    const float* g2w = (const float*)d_in[8];
    const float* g2b = (const float*)d_in[9];
    const float* fcw = (const float*)d_in[10];
    const float* fcb = (const float*)d_in[11];
    float* out = (float*)d_out;

    // fork: single fused prep kernel on side stream
    cudaEventRecord(g_ev0, 0);
    cudaStreamWaitEvent(g_s2, g_ev0, 0);
    cudaMemsetAsync(g_cnt_addr, 0, sizeof(unsigned), g_s2);
    prep_kernel<<<PREP_BLOCKS, 1024, 0, g_s2>>>(ei, ei + EE);
    cudaEventRecord(g_evScat, g_s2);

    // main stream: conv1 overlaps prep; init out (tiny) too
    conv1_kernel<<<dim3(8, BB), 128>>>(x, w1, b1);
    init_out_kernel<<<BB, 6>>>(fcb, out);
    cudaStreamWaitEvent(0, g_evScat, 0);          // conv2 needs dinv; gathers need CSR
    conv2_kernel<<<dim3(4, BB), 256>>>(w2, b2);

    // fused GCN layers
    gcn1_fused_kernel<<<NN / 16, 256>>>(g1w, g1b);       // 2 nodes/warp
    gcn2_pool_kernel<<<NN / 16, 256>>>(g2w, g2b, fcw, out);  // 2 nodes/warp + pooled FC
}

// round 14
// speedup vs baseline: 1.1852x; 1.0236x over previous
#include <cuda_runtime.h>
#include <cuda_fp16.h>
#include <cstdint>

#define BB   256
#define TT   2048
#define FIN  9
#define T1   1024
#define TPP  512
#define NN   131072
#define EE   2097152
#define HID  64
#define TW   260
#define PREP_BLOCKS 128

// ---------------- scratch (static device globals; no runtime alloc) ----------
__device__ int      d_cnt[NN];
__device__ int      d_ptr[NN];
__device__ int      d_cur[NN];
__device__ int      d_bsum[PREP_BLOCKS];
__device__ int      d_srow[EE];
__device__ float    d_dinv[NN];
__device__ float    d_h1[(size_t)BB * 16 * T1];   // conv1 output, CHANNEL-MAJOR [b][c][t]
__device__ __align__(16) __half d_g16[(size_t)NN * 32];    // layer-1 gather input (fp16)
__device__ __align__(16) __half d_gB16[(size_t)NN * HID];  // layer-2 gather input (fp16)
__device__ unsigned g_cnt;                        // grid barrier counter (memset per launch)

// ---------------- streams/events for capture fork/join ----------------------
static cudaStream_t g_s2;
static cudaEvent_t  g_ev0, g_evScat;
static void*        g_cnt_addr;
namespace {
struct StreamInit {
    StreamInit() {
        cudaStreamCreateWithFlags(&g_s2, cudaStreamNonBlocking);
        cudaEventCreateWithFlags(&g_ev0,    cudaEventDisableTiming);
        cudaEventCreateWithFlags(&g_evScat, cudaEventDisableTiming);
        cudaGetSymbolAddress(&g_cnt_addr, g_cnt);
    }
} g_streamInit;
}

// ---------------- grid barrier (single-wave, monotonic counter) --------------
__device__ __forceinline__ void gridbar(unsigned& phase) {
    __syncthreads();
    if (threadIdx.x == 0) {
        __threadfence();
        atomicAdd(&g_cnt, 1u);
        unsigned target = (++phase) * gridDim.x;
        while (atomicAdd(&g_cnt, 0u) < target) __nanosleep(64);
        __threadfence();
    }
    __syncthreads();
}

// ---------------- fused graph prep: zero+hist+scan+finalize+scatter ----------
__global__ void __launch_bounds__(1024)
prep_kernel(const int* __restrict__ row, const int* __restrict__ col) {
    __shared__ int s[1024];
    __shared__ int sb[PREP_BLOCKS];
    int tid = threadIdx.x, bid = blockIdx.x;
    int i = bid * 1024 + tid;
    unsigned phase = 0;

    d_cnt[i] = 0;
    gridbar(phase);

    #pragma unroll
    for (int j = 0; j < EE / NN; j++)
        atomicAdd(&d_cnt[col[i + j * NN]], 1);
    gridbar(phase);

    int v = d_cnt[i];
    s[tid] = v;
    __syncthreads();
    #pragma unroll
    for (int off = 1; off < 1024; off <<= 1) {
        int t = (tid >= off) ? s[tid - off] : 0;
        __syncthreads();
        s[tid] += t;
        __syncthreads();
    }
    int le = s[tid] - v;
    if (tid == 1023) d_bsum[bid] = s[1023];
    gridbar(phase);

    if (tid < PREP_BLOCKS) sb[tid] = d_bsum[tid];
    __syncthreads();
    #pragma unroll
    for (int off = 1; off < PREP_BLOCKS; off <<= 1) {
        int t = (tid < PREP_BLOCKS && tid >= off) ? sb[tid - off] : 0;
        __syncthreads();
        if (tid < PREP_BLOCKS) sb[tid] += t;
        __syncthreads();
    }
    int bex = (bid == 0) ? 0 : sb[bid - 1];

    int p = le + bex;
    d_ptr[i] = p;
    d_cur[i] = p;
    d_dinv[i] = rsqrtf((float)v + 1.0f);
    gridbar(phase);

    #pragma unroll
    for (int j = 0; j < EE / NN; j++) {
        int e = i + j * NN;
        int c = col[e];
        int q = atomicAdd(&d_cur[c], 1);
        d_srow[q] = row[e];
    }
}

// ---------------- conv1: (B,T,9) -> relu -> pool2 -> d_h1 [b][c][t] ----------
__global__ void conv1_kernel(const float* __restrict__ x,
                             const float* __restrict__ w,
                             const float* __restrict__ bias) {
    __shared__ __align__(16) float xs[TW * 9];
    __shared__ __align__(16) float ws[720];
    __shared__ float bs[16];
    int b = blockIdx.y, tp0 = blockIdx.x * 128, tid = threadIdx.x;

    for (int j = tid; j < 720; j += 128) {
        int c = j & 15, r = j >> 4, f = r / 5, k = r - f * 5;
        ws[j] = w[c * 45 + f * 5 + k];
    }
    if (tid < 16) bs[tid] = bias[tid];

    int base = 2 * tp0 - 2;
    const float* xb = x + (size_t)b * TT * FIN;
    for (int j = tid; j < TW * 9; j += 128) {
        int t = base + j / 9, f = j - (j / 9) * 9;
        xs[j] = (t >= 0 && t < TT) ? xb[t * 9 + f] : 0.0f;
    }
    __syncthreads();

    float s0[16], s1[16];
    #pragma unroll
    for (int c = 0; c < 16; c++) { s0[c] = 0.f; s1[c] = 0.f; }

    #pragma unroll
    for (int f = 0; f < 9; f++) {
        float v[6];
        #pragma unroll
        for (int j = 0; j < 6; j++) v[j] = xs[(2 * tid + j) * 9 + f];
        #pragma unroll
        for (int k = 0; k < 5; k++) {
            const float4* wr = (const float4*)&ws[(f * 5 + k) * 16];
            float a = v[k], bb = v[k + 1];
            #pragma unroll
            for (int q = 0; q < 4; q++) {
                float4 w4 = wr[q];
                s0[q*4+0] += w4.x * a;  s1[q*4+0] += w4.x * bb;
                s0[q*4+1] += w4.y * a;  s1[q*4+1] += w4.y * bb;
                s0[q*4+2] += w4.z * a;  s1[q*4+2] += w4.z * bb;
                s0[q*4+3] += w4.w * a;  s1[q*4+3] += w4.w * bb;
            }
        }
    }

    float* hb = d_h1 + (size_t)b * 16 * T1 + tp0 + tid;
    #pragma unroll
    for (int c = 0; c < 16; c++)
        hb[c * T1] = fmaxf(fmaxf(s0[c], s1[c]) + bs[c], 0.f);
}

// ------- conv2 (8pos x 4ch tile, occ-hinted): d_h1 -> g16 = fp16(dinv*h2) ---
__global__ void __launch_bounds__(256, 5)
conv2_kernel(const float* __restrict__ w2, const float* __restrict__ b2) {
    __shared__ __align__(16) float buf[16 * TW];
    __shared__ __align__(16) float ws[2560];        // [(ci*5+k)*32 + c]
    __shared__ float bs[32];
    int b = blockIdx.y, tid = threadIdx.x;
    int cg = tid & 7, pg = tid >> 3;                // 8 ch-groups x 32 pos-groups
    int t0 = blockIdx.x * 256;

    for (int j = tid; j < 2560; j += 256) {
        int c = j & 31, r = j >> 5;
        ws[j] = w2[c * 80 + r];
    }
    if (tid < 32) bs[tid] = b2[tid];

    int base = t0 - 2;
    const float* hb = d_h1 + (size_t)b * 16 * T1;
    #pragma unroll
    for (int ci = 0; ci < 16; ci++)
        for (int j = tid; j < TW; j += 256) {
            int t = base + j;
            buf[ci * TW + j] = (t >= 0 && t < T1) ? hb[ci * T1 + t] : 0.f;
        }
    __syncthreads();

    float acc[32];                                  // [p 0..7][cc 0..3]
    #pragma unroll
    for (int o = 0; o < 32; o++) acc[o] = 0.f;

    #pragma unroll 4
    for (int ci = 0; ci < 16; ci++) {
        float v[12];
        const float4* vp = (const float4*)(buf + ci * TW + pg * 8);
        #pragma unroll
        for (int q = 0; q < 3; q++) {
            float4 t4 = vp[q];
            v[q*4+0] = t4.x; v[q*4+1] = t4.y; v[q*4+2] = t4.z; v[q*4+3] = t4.w;
        }
        #pragma unroll
        for (int k = 0; k < 5; k++) {
            float4 w4 = *(const float4*)&ws[(ci * 5 + k) * 32 + cg * 4];
            #pragma unroll
            for (int p = 0; p < 8; p++) {
                float a = v[p + k];
                acc[p*4+0] += a * w4.x;
                acc[p*4+1] += a * w4.y;
                acc[p*4+2] += a * w4.z;
                acc[p*4+3] += a * w4.w;
            }
        }
    }

    int nbase = b * TPP + (t0 >> 1) + pg * 4;
    #pragma unroll
    for (int pp = 0; pp < 4; pp++) {
        int n = nbase + pp;
        float dv = d_dinv[n];
        int pa = pp * 8, pb = pa + 4;
        float c0 = fmaxf(fmaxf(acc[pa+0], acc[pb+0]) + bs[cg*4+0], 0.f) * dv;
        float c1 = fmaxf(fmaxf(acc[pa+1], acc[pb+1]) + bs[cg*4+1], 0.f) * dv;
        float c2 = fmaxf(fmaxf(acc[pa+2], acc[pb+2]) + bs[cg*4+2], 0.f) * dv;
        float c3 = fmaxf(fmaxf(acc[pa+3], acc[pb+3]) + bs[cg*4+3], 0.f) * dv;
        __half2* o = (__half2*)(d_g16 + (size_t)n * 32 + cg * 4);
        o[0] = __floats2half2_rn(c0, c1);
        o[1] = __floats2half2_rn(c2, c3);
    }
}

// ------- fused layer 1: 4 nodes/warp (quarter-warp each) + GEMM 32->64 ------
// Row = 32ch fp16 = 64B = 8 lanes x uint2 (4 ch each).
__global__ void gcn1_fused_kernel(const float* __restrict__ w,
                                  const float* __restrict__ bias) {
    __shared__ __align__(16) float ws[2048];     // W1 [c][o], 32x64
    __shared__ float bs[64];
    __shared__ __align__(16) float st[8][128];   // per-warp: 4 nodes x 32 ch
    int tid = threadIdx.x;
    for (int j = tid; j < 2048; j += 256) ws[j] = w[j];
    if (tid < 64) bs[tid] = bias[tid];
    __syncthreads();

    int warp = tid >> 5, lane = tid & 31;
    int q = lane >> 3, ql = lane & 7;            // quarter id, lane-in-quarter
    int nbase = (blockIdx.x * 8 + warp) * 4;
    int n = nbase + q;
    int p = d_ptr[n];
    int cnt = d_cnt[n];
    const uint2* gp = (const uint2*)d_g16 + ql;  // +r*8 selects row r (64B rows)

    // self loop (lane covers channels 4*ql .. 4*ql+3)
    float a0, a1, a2, a3;
    {
        uint2 v = gp[n << 3];
        float2 fa = __half22float2(*(const __half2*)&v.x);
        float2 fb = __half22float2(*(const __half2*)&v.y);
        a0 = fa.x; a1 = fa.y; a2 = fb.x; a3 = fb.y;
    }

    int e = 0;
    for (; e + 4 <= cnt; e += 4) {
        int r0 = d_srow[p+e], r1 = d_srow[p+e+1], r2 = d_srow[p+e+2], r3 = d_srow[p+e+3];
        uint2 v0 = gp[r0 << 3];
        uint2 v1 = gp[r1 << 3];
        uint2 v2 = gp[r2 << 3];
        uint2 v3 = gp[r3 << 3];
        float2 f0a = __half22float2(*(const __half2*)&v0.x), f0b = __half22float2(*(const __half2*)&v0.y);
        float2 f1a = __half22float2(*(const __half2*)&v1.x), f1b = __half22float2(*(const __half2*)&v1.y);
        float2 f2a = __half22float2(*(const __half2*)&v2.x), f2b = __half22float2(*(const __half2*)&v2.y);
        float2 f3a = __half22float2(*(const __half2*)&v3.x), f3b = __half22float2(*(const __half2*)&v3.y);
        a0 += (f0a.x + f1a.x) + (f2a.x + f3a.x);
        a1 += (f0a.y + f1a.y) + (f2a.y + f3a.y);
        a2 += (f0b.x + f1b.x) + (f2b.x + f3b.x);
        a3 += (f0b.y + f1b.y) + (f2b.y + f3b.y);
    }
    for (; e < cnt; e++) {
        int r = d_srow[p + e];
        uint2 v = gp[r << 3];
        float2 fa = __half22float2(*(const __half2*)&v.x);
        float2 fb = __half22float2(*(const __half2*)&v.y);
        a0 += fa.x; a1 += fa.y; a2 += fb.x; a3 += fb.y;
    }

    *(float4*)&st[warp][q * 32 + 4 * ql] = make_float4(a0, a1, a2, a3);
    __syncwarp();

    // epilogue: 4 nodes, full warp; lane -> channels 2*lane, 2*lane+1
    #pragma unroll
    for (int k = 0; k < 4; k++) {
        int nk = nbase + k;
        float s0 = 0.f, s1 = 0.f;
        #pragma unroll
        for (int c = 0; c < 32; c++) {
            float v = st[warp][k * 32 + c];
            float2 wp = ((const float2*)&ws[c * 64])[lane];
            s0 += v * wp.x;
            s1 += v * wp.y;
        }
        float dv = d_dinv[nk];
        float o0 = fmaxf(dv * s0 + bs[2 * lane],     0.f) * dv;
        float o1 = fmaxf(dv * s1 + bs[2 * lane + 1], 0.f) * dv;
        ((__half2*)d_gB16)[(nk << 5) + lane] = __floats2half2_rn(o0, o1);
    }
}

// ---------------- init out = fcb (per replay, before atomics) ----------------
__global__ void init_out_kernel(const float* __restrict__ fcb, float* __restrict__ out) {
    out[blockIdx.x * 6 + threadIdx.x] = fcb[threadIdx.x];
}

// ------- fused layer 2 + pool + FC: 4 nodes/warp + GEMM + pooled FC ---------
// Row = 64ch fp16 = 128B = 8 lanes x uint4 (8 ch each).
// Block = 32 consecutive nodes (batch b = blockIdx.x >> 4).
__global__ void gcn2_pool_kernel(const float* __restrict__ w,
                                 const float* __restrict__ bias,
                                 const float* __restrict__ fcw,
                                 float* __restrict__ out) {
    __shared__ __align__(16) float ws[4096];     // W2 [c][o], 64x64
    __shared__ float bs[64];
    __shared__ float fw[384];                    // fcW [o][k], 6x64
    __shared__ __align__(16) float st[8][256];   // per-warp: 4 nodes x 64 ch
    __shared__ float po[6];                      // block-level pooled partials
    int tid = threadIdx.x;
    for (int j = tid; j < 4096; j += 256) ws[j] = w[j];
    if (tid < 64) bs[tid] = bias[tid];
    else if (tid >= 64 && tid < 70) po[tid - 64] = 0.f;
    for (int j = tid; j < 384; j += 256) fw[j] = fcw[j];
    __syncthreads();

    int warp = tid >> 5, lane = tid & 31;
    int q = lane >> 3, ql = lane & 7;            // quarter id, lane-in-quarter
    int nbase = blockIdx.x * 32 + warp * 4;
    int n = nbase + q;
    int p = d_ptr[n];
    int cnt = d_cnt[n];
    const uint4* gp = (const uint4*)d_gB16 + ql; // +r*8 selects row r (128B rows)

    // self loop (lane covers channels 8*ql .. 8*ql+7)
    float a[8];
    {
        uint4 v = gp[n << 3];
        const __half2* h = (const __half2*)&v;
        #pragma unroll
        for (int j = 0; j < 4; j++) {
            float2 f = __half22float2(h[j]);
            a[2*j] = f.x; a[2*j+1] = f.y;
        }
    }

    int e = 0;
    for (; e + 2 <= cnt; e += 2) {
        int r0 = d_srow[p+e], r1 = d_srow[p+e+1];
        uint4 v0 = gp[r0 << 3];
        uint4 v1 = gp[r1 << 3];
        const __half2* h0 = (const __half2*)&v0;
        const __half2* h1 = (const __half2*)&v1;
        #pragma unroll
        for (int j = 0; j < 4; j++) {
            float2 f0 = __half22float2(h0[j]);
            float2 f1 = __half22float2(h1[j]);
            a[2*j]   += f0.x + f1.x;
            a[2*j+1] += f0.y + f1.y;
        }
    }
    for (; e < cnt; e++) {
        int r = d_srow[p + e];
        uint4 v = gp[r << 3];
        const __half2* h = (const __half2*)&v;
        #pragma unroll
        for (int j = 0; j < 4; j++) {
            float2 f = __half22float2(h[j]);
            a[2*j] += f.x; a[2*j+1] += f.y;
        }
    }

    *(float4*)&st[warp][q * 64 + 8 * ql]     = make_float4(a[0], a[1], a[2], a[3]);
    *(float4*)&st[warp][q * 64 + 8 * ql + 4] = make_float4(a[4], a[5], a[6], a[7]);
    __syncwarp();

    // epilogue: GEMM 64->64 + relu for all 4 nodes; FC partials accumulated,
    // single butterfly reduce at the end.
    float f6[6];
    #pragma unroll
    for (int o = 0; o < 6; o++) f6[o] = 0.f;

    #pragma unroll
    for (int k = 0; k < 4; k++) {
        int nk = nbase + k;
        float s0 = 0.f, s1 = 0.f;
        #pragma unroll
        for (int c = 0; c < 64; c++) {
            float v = st[warp][k * 64 + c];
            float2 wp = ((const float2*)&ws[c * 64])[lane];
            s0 += v * wp.x;
            s1 += v * wp.y;
        }
        float dv = d_dinv[nk];
        float h0 = fmaxf(dv * s0 + bs[2 * lane],     0.f);
        float h1 = fmaxf(dv * s1 + bs[2 * lane + 1], 0.f);

        #pragma unroll
        for (int o = 0; o < 6; o++)
            f6[o] += h0 * fw[o * 64 + 2 * lane] + h1 * fw[o * 64 + 2 * lane + 1];
    }

    #pragma unroll
    for (int o = 0; o < 6; o++) {
        float c6 = f6[o];
        c6 += __shfl_xor_sync(0xffffffffu, c6, 1);
        c6 += __shfl_xor_sync(0xffffffffu, c6, 2);
        c6 += __shfl_xor_sync(0xffffffffu, c6, 4);
        c6 += __shfl_xor_sync(0xffffffffu, c6, 8);
        c6 += __shfl_xor_sync(0xffffffffu, c6, 16);
        if (lane == 0) atomicAdd(&po[o], c6);
    }

    __syncthreads();
    if (tid < 6)
        atomicAdd(&out[(blockIdx.x >> 4) * 6 + tid], po[tid] * (1.0f / TPP));
}

// ---------------- launch -----------------------------------------------------
extern "C" void kernel_launch(void* const* d_in, const int* in_sizes, int n_in,
                              void* d_out, int out_size) {
    const float* x   = (const float*)d_in[0];
    const int*   ei  = (const int*)  d_in[1];
    const float* w1  = (const float*)d_in[2];
    const float* b1  = (const float*)d_in[3];
    const float* w2  = (const float*)d_in[4];
    const float* b2  = (const float*)d_in[5];
    const float* g1w = (const float*)d_in[6];
    const float* g1b = (const float*)d_in[7];
    const float* g2w = (const float*)d_in[8];
    const float* g2b = (const float*)d_in[9];
    const float* fcw = (const float*)d_in[10];
    const float* fcb = (const float*)d_in[11];
    float* out = (float*)d_out;

    // fork: single fused prep kernel on side stream
    cudaEventRecord(g_ev0, 0);
    cudaStreamWaitEvent(g_s2, g_ev0, 0);
    cudaMemsetAsync(g_cnt_addr, 0, sizeof(unsigned), g_s2);
    prep_kernel<<<PREP_BLOCKS, 1024, 0, g_s2>>>(ei, ei + EE);
    cudaEventRecord(g_evScat, g_s2);

    // main stream: conv1 overlaps prep; init out (tiny) too
    conv1_kernel<<<dim3(8, BB), 128>>>(x, w1, b1);
    init_out_kernel<<<BB, 6>>>(fcb, out);
    cudaStreamWaitEvent(0, g_evScat, 0);          // conv2 needs dinv; gathers need CSR
    conv2_kernel<<<dim3(4, BB), 256>>>(w2, b2);

    // fused GCN layers (4 nodes/warp quarter-warp gathers)
    gcn1_fused_kernel<<<NN / 32, 256>>>(g1w, g1b);
    gcn2_pool_kernel<<<NN / 32, 256>>>(g2w, g2b, fcw, out);
}

// round 15
// speedup vs baseline: 1.2504x; 1.0550x over previous
#include <cuda_runtime.h>
#include <cuda_fp16.h>
#include <cstdint>

#define BB   256
#define TT   2048
#define FIN  9
#define T1   1024
#define TPP  512
#define NN   131072
#define EE   2097152
#define HID  64
#define TW   260
#define PREP_BLOCKS 128

// ---------------- scratch (static device globals; no runtime alloc) ----------
__device__ int      d_cnt[NN];
__device__ int      d_ptr[NN];
__device__ int      d_cur[NN];
__device__ int      d_bsum[PREP_BLOCKS];
__device__ int      d_srow[EE];
__device__ float    d_dinv[NN];
__device__ float    d_h1[(size_t)BB * 16 * T1];   // conv1 output, CHANNEL-MAJOR [b][c][t]
__device__ __align__(16) __half d_g16[(size_t)NN * 32];    // layer-1 gather input (fp16)
__device__ __align__(16) __half d_gB16[(size_t)NN * HID];  // layer-2 gather input (fp16)
__device__ unsigned g_cnt;                        // grid barrier counter (memset per launch)

// ---------------- streams/events for capture fork/join ----------------------
static cudaStream_t g_s2;
static cudaEvent_t  g_ev0, g_evScat;
static void*        g_cnt_addr;
namespace {
struct StreamInit {
    StreamInit() {
        cudaStreamCreateWithFlags(&g_s2, cudaStreamNonBlocking);
        cudaEventCreateWithFlags(&g_ev0,    cudaEventDisableTiming);
        cudaEventCreateWithFlags(&g_evScat, cudaEventDisableTiming);
        cudaGetSymbolAddress(&g_cnt_addr, g_cnt);
    }
} g_streamInit;
}

// ---------------- grid barrier (single-wave, monotonic counter) --------------
__device__ __forceinline__ void gridbar(unsigned& phase) {
    __syncthreads();
    if (threadIdx.x == 0) {
        __threadfence();
        atomicAdd(&g_cnt, 1u);
        unsigned target = (++phase) * gridDim.x;
        while (atomicAdd(&g_cnt, 0u) < target) __nanosleep(64);
        __threadfence();
    }
    __syncthreads();
}

// ---------------- fused graph prep: zero+hist+scan+finalize+scatter ----------
__global__ void __launch_bounds__(1024)
prep_kernel(const int* __restrict__ row, const int* __restrict__ col) {
    __shared__ int s[1024];
    __shared__ int sb[PREP_BLOCKS];
    int tid = threadIdx.x, bid = blockIdx.x;
    int i = bid * 1024 + tid;
    unsigned phase = 0;

    d_cnt[i] = 0;
    gridbar(phase);

    #pragma unroll
    for (int j = 0; j < EE / NN; j++)
        atomicAdd(&d_cnt[col[i + j * NN]], 1);
    gridbar(phase);

    int v = d_cnt[i];
    s[tid] = v;
    __syncthreads();
    #pragma unroll
    for (int off = 1; off < 1024; off <<= 1) {
        int t = (tid >= off) ? s[tid - off] : 0;
        __syncthreads();
        s[tid] += t;
        __syncthreads();
    }
    int le = s[tid] - v;
    if (tid == 1023) d_bsum[bid] = s[1023];
    gridbar(phase);

    if (tid < PREP_BLOCKS) sb[tid] = d_bsum[tid];
    __syncthreads();
    #pragma unroll
    for (int off = 1; off < PREP_BLOCKS; off <<= 1) {
        int t = (tid < PREP_BLOCKS && tid >= off) ? sb[tid - off] : 0;
        __syncthreads();
        if (tid < PREP_BLOCKS) sb[tid] += t;
        __syncthreads();
    }
    int bex = (bid == 0) ? 0 : sb[bid - 1];

    int p = le + bex;
    d_ptr[i] = p;
    d_cur[i] = p;
    d_dinv[i] = rsqrtf((float)v + 1.0f);
    gridbar(phase);

    #pragma unroll
    for (int j = 0; j < EE / NN; j++) {
        int e = i + j * NN;
        int c = col[e];
        int q = atomicAdd(&d_cur[c], 1);
        d_srow[q] = row[e];
    }
}

// ---------------- conv1: (B,T,9) -> relu -> pool2 -> d_h1 [b][c][t] ----------
__global__ void conv1_kernel(const float* __restrict__ x,
                             const float* __restrict__ w,
                             const float* __restrict__ bias) {
    __shared__ __align__(16) float xs[TW * 9];
    __shared__ __align__(16) float ws[720];
    __shared__ float bs[16];
    int b = blockIdx.y, tp0 = blockIdx.x * 128, tid = threadIdx.x;

    for (int j = tid; j < 720; j += 128) {
        int c = j & 15, r = j >> 4, f = r / 5, k = r - f * 5;
        ws[j] = w[c * 45 + f * 5 + k];
    }
    if (tid < 16) bs[tid] = bias[tid];

    int base = 2 * tp0 - 2;
    const float* xb = x + (size_t)b * TT * FIN;
    for (int j = tid; j < TW * 9; j += 128) {
        int t = base + j / 9, f = j - (j / 9) * 9;
        xs[j] = (t >= 0 && t < TT) ? xb[t * 9 + f] : 0.0f;
    }
    __syncthreads();

    float s0[16], s1[16];
    #pragma unroll
    for (int c = 0; c < 16; c++) { s0[c] = 0.f; s1[c] = 0.f; }

    #pragma unroll
    for (int f = 0; f < 9; f++) {
        float v[6];
        #pragma unroll
        for (int j = 0; j < 6; j++) v[j] = xs[(2 * tid + j) * 9 + f];
        #pragma unroll
        for (int k = 0; k < 5; k++) {
            const float4* wr = (const float4*)&ws[(f * 5 + k) * 16];
            float a = v[k], bb = v[k + 1];
            #pragma unroll
            for (int q = 0; q < 4; q++) {
                float4 w4 = wr[q];
                s0[q*4+0] += w4.x * a;  s1[q*4+0] += w4.x * bb;
                s0[q*4+1] += w4.y * a;  s1[q*4+1] += w4.y * bb;
                s0[q*4+2] += w4.z * a;  s1[q*4+2] += w4.z * bb;
                s0[q*4+3] += w4.w * a;  s1[q*4+3] += w4.w * bb;
            }
        }
    }

    float* hb = d_h1 + (size_t)b * 16 * T1 + tp0 + tid;
    #pragma unroll
    for (int c = 0; c < 16; c++)
        hb[c * T1] = fmaxf(fmaxf(s0[c], s1[c]) + bs[c], 0.f);
}

// ------- conv2 (8pos x 4ch tile): d_h1 [b][c][t] -> g16 = fp16(dinv*h2) -----
__global__ void __launch_bounds__(256)
conv2_kernel(const float* __restrict__ w2, const float* __restrict__ b2) {
    __shared__ __align__(16) float buf[16 * TW];
    __shared__ __align__(16) float ws[2560];        // [(ci*5+k)*32 + c]
    __shared__ float bs[32];
    int b = blockIdx.y, tid = threadIdx.x;
    int cg = tid & 7, pg = tid >> 3;                // 8 ch-groups x 32 pos-groups
    int t0 = blockIdx.x * 256;

    for (int j = tid; j < 2560; j += 256) {
        int c = j & 31, r = j >> 5;
        ws[j] = w2[c * 80 + r];
    }
    if (tid < 32) bs[tid] = b2[tid];

    int base = t0 - 2;
    const float* hb = d_h1 + (size_t)b * 16 * T1;
    #pragma unroll
    for (int ci = 0; ci < 16; ci++)
        for (int j = tid; j < TW; j += 256) {
            int t = base + j;
            buf[ci * TW + j] = (t >= 0 && t < T1) ? hb[ci * T1 + t] : 0.f;
        }
    __syncthreads();

    float acc[32];                                  // [p 0..7][cc 0..3]
    #pragma unroll
    for (int o = 0; o < 32; o++) acc[o] = 0.f;

    #pragma unroll 4
    for (int ci = 0; ci < 16; ci++) {
        float v[12];
        const float4* vp = (const float4*)(buf + ci * TW + pg * 8);
        #pragma unroll
        for (int q = 0; q < 3; q++) {
            float4 t4 = vp[q];
            v[q*4+0] = t4.x; v[q*4+1] = t4.y; v[q*4+2] = t4.z; v[q*4+3] = t4.w;
        }
        #pragma unroll
        for (int k = 0; k < 5; k++) {
            float4 w4 = *(const float4*)&ws[(ci * 5 + k) * 32 + cg * 4];
            #pragma unroll
            for (int p = 0; p < 8; p++) {
                float a = v[p + k];
                acc[p*4+0] += a * w4.x;
                acc[p*4+1] += a * w4.y;
                acc[p*4+2] += a * w4.z;
                acc[p*4+3] += a * w4.w;
            }
        }
    }

    int nbase = b * TPP + (t0 >> 1) + pg * 4;
    #pragma unroll
    for (int pp = 0; pp < 4; pp++) {
        int n = nbase + pp;
        float dv = d_dinv[n];
        int pa = pp * 8, pb = pa + 4;
        float c0 = fmaxf(fmaxf(acc[pa+0], acc[pb+0]) + bs[cg*4+0], 0.f) * dv;
        float c1 = fmaxf(fmaxf(acc[pa+1], acc[pb+1]) + bs[cg*4+1], 0.f) * dv;
        float c2 = fmaxf(fmaxf(acc[pa+2], acc[pb+2]) + bs[cg*4+2], 0.f) * dv;
        float c3 = fmaxf(fmaxf(acc[pa+3], acc[pb+3]) + bs[cg*4+3], 0.f) * dv;
        __half2* o = (__half2*)(d_g16 + (size_t)n * 32 + cg * 4);
        o[0] = __floats2half2_rn(c0, c1);
        o[1] = __floats2half2_rn(c2, c3);
    }
}

// ------- fused layer 1: 4 nodes/warp (quarter-warp each) + GEMM 32->64 ------
// Row = 32ch fp16 = 64B = 8 lanes x uint2 (4 ch each).
__global__ void gcn1_fused_kernel(const float* __restrict__ w,
                                  const float* __restrict__ bias) {
    __shared__ __align__(16) float ws[2048];     // W1 [c][o], 32x64
    __shared__ float bs[64];
    __shared__ __align__(16) float st[8][128];   // per-warp: 4 nodes x 32 ch
    int tid = threadIdx.x;
    for (int j = tid; j < 2048; j += 256) ws[j] = w[j];
    if (tid < 64) bs[tid] = bias[tid];
    __syncthreads();

    int warp = tid >> 5, lane = tid & 31;
    int q = lane >> 3, ql = lane & 7;            // quarter id, lane-in-quarter
    int nbase = (blockIdx.x * 8 + warp) * 4;
    int n = nbase + q;
    int p = d_ptr[n];
    int cnt = d_cnt[n];
    const uint2* gp = (const uint2*)d_g16 + ql;  // +r*8 selects row r (64B rows)

    // self loop (lane covers channels 4*ql .. 4*ql+3)
    float a0, a1, a2, a3;
    {
        uint2 v = gp[n << 3];
        float2 fa = __half22float2(*(const __half2*)&v.x);
        float2 fb = __half22float2(*(const __half2*)&v.y);
        a0 = fa.x; a1 = fa.y; a2 = fb.x; a3 = fb.y;
    }

    int e = 0;
    for (; e + 4 <= cnt; e += 4) {
        int r0 = d_srow[p+e], r1 = d_srow[p+e+1], r2 = d_srow[p+e+2], r3 = d_srow[p+e+3];
        uint2 v0 = gp[r0 << 3];
        uint2 v1 = gp[r1 << 3];
        uint2 v2 = gp[r2 << 3];
        uint2 v3 = gp[r3 << 3];
        float2 f0a = __half22float2(*(const __half2*)&v0.x), f0b = __half22float2(*(const __half2*)&v0.y);
        float2 f1a = __half22float2(*(const __half2*)&v1.x), f1b = __half22float2(*(const __half2*)&v1.y);
        float2 f2a = __half22float2(*(const __half2*)&v2.x), f2b = __half22float2(*(const __half2*)&v2.y);
        float2 f3a = __half22float2(*(const __half2*)&v3.x), f3b = __half22float2(*(const __half2*)&v3.y);
        a0 += (f0a.x + f1a.x) + (f2a.x + f3a.x);
        a1 += (f0a.y + f1a.y) + (f2a.y + f3a.y);
        a2 += (f0b.x + f1b.x) + (f2b.x + f3b.x);
        a3 += (f0b.y + f1b.y) + (f2b.y + f3b.y);
    }
    for (; e < cnt; e++) {
        int r = d_srow[p + e];
        uint2 v = gp[r << 3];
        float2 fa = __half22float2(*(const __half2*)&v.x);
        float2 fb = __half22float2(*(const __half2*)&v.y);
        a0 += fa.x; a1 += fa.y; a2 += fb.x; a3 += fb.y;
    }

    *(float4*)&st[warp][q * 32 + 4 * ql] = make_float4(a0, a1, a2, a3);
    __syncwarp();

    // epilogue: 4 nodes, full warp; lane -> channels 2*lane, 2*lane+1
    #pragma unroll
    for (int k = 0; k < 4; k++) {
        int nk = nbase + k;
        float s0 = 0.f, s1 = 0.f;
        #pragma unroll
        for (int c = 0; c < 32; c++) {
            float v = st[warp][k * 32 + c];
            float2 wp = ((const float2*)&ws[c * 64])[lane];
            s0 += v * wp.x;
            s1 += v * wp.y;
        }
        float dv = d_dinv[nk];
        float o0 = fmaxf(dv * s0 + bs[2 * lane],     0.f) * dv;
        float o1 = fmaxf(dv * s1 + bs[2 * lane + 1], 0.f) * dv;
        ((__half2*)d_gB16)[(nk << 5) + lane] = __floats2half2_rn(o0, o1);
    }
}

// ---------------- init out = fcb (per replay, before atomics) ----------------
__global__ void init_out_kernel(const float* __restrict__ fcb, float* __restrict__ out) {
    out[blockIdx.x * 6 + threadIdx.x] = fcb[threadIdx.x];
}

// ------- fused layer 2 + pool + FC: 4 nodes/warp + GEMM + pooled FC ---------
// Row = 64ch fp16 = 128B = 8 lanes x uint4 (8 ch each).
// Block = 32 consecutive nodes (batch b = blockIdx.x >> 4).
__global__ void gcn2_pool_kernel(const float* __restrict__ w,
                                 const float* __restrict__ bias,
                                 const float* __restrict__ fcw,
                                 float* __restrict__ out) {
    __shared__ __align__(16) float ws[4096];     // W2 [c][o], 64x64
    __shared__ float bs[64];
    __shared__ float fw[384];                    // fcW [o][k], 6x64
    __shared__ __align__(16) float st[8][256];   // per-warp: 4 nodes x 64 ch
    __shared__ float po[6];                      // block-level pooled partials
    int tid = threadIdx.x;
    for (int j = tid; j < 4096; j += 256) ws[j] = w[j];
    if (tid < 64) bs[tid] = bias[tid];
    else if (tid >= 64 && tid < 70) po[tid - 64] = 0.f;
    for (int j = tid; j < 384; j += 256) fw[j] = fcw[j];
    __syncthreads();

    int warp = tid >> 5, lane = tid & 31;
    int q = lane >> 3, ql = lane & 7;            // quarter id, lane-in-quarter
    int nbase = blockIdx.x * 32 + warp * 4;
    int n = nbase + q;
    int p = d_ptr[n];
    int cnt = d_cnt[n];
    const uint4* gp = (const uint4*)d_gB16 + ql; // +r*8 selects row r (128B rows)

    // self loop (lane covers channels 8*ql .. 8*ql+7)
    float a[8];
    {
        uint4 v = gp[n << 3];
        const __half2* h = (const __half2*)&v;
        #pragma unroll
        for (int j = 0; j < 4; j++) {
            float2 f = __half22float2(h[j]);
            a[2*j] = f.x; a[2*j+1] = f.y;
        }
    }

    int e = 0;
    for (; e + 2 <= cnt; e += 2) {
        int r0 = d_srow[p+e], r1 = d_srow[p+e+1];
        uint4 v0 = gp[r0 << 3];
        uint4 v1 = gp[r1 << 3];
        const __half2* h0 = (const __half2*)&v0;
        const __half2* h1 = (const __half2*)&v1;
        #pragma unroll
        for (int j = 0; j < 4; j++) {
            float2 f0 = __half22float2(h0[j]);
            float2 f1 = __half22float2(h1[j]);
            a[2*j]   += f0.x + f1.x;
            a[2*j+1] += f0.y + f1.y;
        }
    }
    for (; e < cnt; e++) {
        int r = d_srow[p + e];
        uint4 v = gp[r << 3];
        const __half2* h = (const __half2*)&v;
        #pragma unroll
        for (int j = 0; j < 4; j++) {
            float2 f = __half22float2(h[j]);
            a[2*j] += f.x; a[2*j+1] += f.y;
        }
    }

    *(float4*)&st[warp][q * 64 + 8 * ql]     = make_float4(a[0], a[1], a[2], a[3]);
    *(float4*)&st[warp][q * 64 + 8 * ql + 4] = make_float4(a[4], a[5], a[6], a[7]);
    __syncwarp();

    // epilogue: GEMM 64->64 + relu for all 4 nodes; FC partials accumulated,
    // single butterfly reduce at the end.
    float f6[6];
    #pragma unroll
    for (int o = 0; o < 6; o++) f6[o] = 0.f;

    #pragma unroll
    for (int k = 0; k < 4; k++) {
        int nk = nbase + k;
        float s0 = 0.f, s1 = 0.f;
        #pragma unroll
        for (int c = 0; c < 64; c++) {
            float v = st[warp][k * 64 + c];
            float2 wp = ((const float2*)&ws[c * 64])[lane];
            s0 += v * wp.x;
            s1 += v * wp.y;
        }
        float dv = d_dinv[nk];
        float h0 = fmaxf(dv * s0 + bs[2 * lane],     0.f);
        float h1 = fmaxf(dv * s1 + bs[2 * lane + 1], 0.f);

        #pragma unroll
        for (int o = 0; o < 6; o++)
            f6[o] += h0 * fw[o * 64 + 2 * lane] + h1 * fw[o * 64 + 2 * lane + 1];
    }

    #pragma unroll
    for (int o = 0; o < 6; o++) {
        float c6 = f6[o];
        c6 += __shfl_xor_sync(0xffffffffu, c6, 1);
        c6 += __shfl_xor_sync(0xffffffffu, c6, 2);
        c6 += __shfl_xor_sync(0xffffffffu, c6, 4);
        c6 += __shfl_xor_sync(0xffffffffu, c6, 8);
        c6 += __shfl_xor_sync(0xffffffffu, c6, 16);
        if (lane == 0) atomicAdd(&po[o], c6);
    }

    __syncthreads();
    if (tid < 6)
        atomicAdd(&out[(blockIdx.x >> 4) * 6 + tid], po[tid] * (1.0f / TPP));
}

// ---------------- launch -----------------------------------------------------
extern "C" void kernel_launch(void* const* d_in, const int* in_sizes, int n_in,
                              void* d_out, int out_size) {
    const float* x   = (const float*)d_in[0];
    const int*   ei  = (const int*)  d_in[1];
    const float* w1  = (const float*)d_in[2];
    const float* b1  = (const float*)d_in[3];
    const float* w2  = (const float*)d_in[4];
    const float* b2  = (const float*)d_in[5];
    const float* g1w = (const float*)d_in[6];
    const float* g1b = (const float*)d_in[7];
    const float* g2w = (const float*)d_in[8];
    const float* g2b = (const float*)d_in[9];
    const float* fcw = (const float*)d_in[10];
    const float* fcb = (const float*)d_in[11];
    float* out = (float*)d_out;

    // fork: single fused prep kernel on side stream
    cudaEventRecord(g_ev0, 0);
    cudaStreamWaitEvent(g_s2, g_ev0, 0);
    cudaMemsetAsync(g_cnt_addr, 0, sizeof(unsigned), g_s2);
    prep_kernel<<<PREP_BLOCKS, 1024, 0, g_s2>>>(ei, ei + EE);
    cudaEventRecord(g_evScat, g_s2);

    // main stream: conv1 overlaps prep; init out (tiny) too
    conv1_kernel<<<dim3(8, BB), 128>>>(x, w1, b1);
    init_out_kernel<<<BB, 6>>>(fcb, out);
    cudaStreamWaitEvent(0, g_evScat, 0);          // conv2 needs dinv; gathers need CSR
    conv2_kernel<<<dim3(4, BB), 256>>>(w2, b2);

    // fused GCN layers (4 nodes/warp quarter-warp gathers)
    gcn1_fused_kernel<<<NN / 32, 256>>>(g1w, g1b);
    gcn2_pool_kernel<<<NN / 32, 256>>>(g2w, g2b, fcw, out);
}

// round 17
// speedup vs baseline: 1.2781x; 1.0222x over previous
#include <cuda_runtime.h>
#include <cuda_fp16.h>
#include <cstdint>

#define BB   256
#define TT   2048
#define FIN  9
#define T1   1024
#define TPP  512
#define NN   131072
#define EE   2097152
#define HID  64
#define TW   260
#define PREP_BLOCKS 128

// ---------------- scratch (static device globals; no runtime alloc) ----------
__device__ int      d_cnt[NN];
__device__ int      d_ptr[NN];
__device__ int      d_cur[NN];
__device__ int      d_bsum[PREP_BLOCKS];
__device__ int      d_srow[EE];
__device__ float    d_dinv[NN];
__device__ float    d_h1[(size_t)BB * 16 * T1];   // conv1 output, CHANNEL-MAJOR [b][c][t]
__device__ __align__(16) __half d_g16[(size_t)NN * 32];    // layer-1 gather input (fp16)
__device__ __align__(16) __half d_gB16[(size_t)NN * HID];  // layer-2 gather input (fp16)
__device__ unsigned g_cnt;                        // grid barrier counter (memset per launch)

// ---------------- streams/events for capture fork/join ----------------------
static cudaStream_t g_s2;
static cudaEvent_t  g_ev0, g_evFin, g_evScat;
static void*        g_cnt_addr;
namespace {
struct StreamInit {
    StreamInit() {
        cudaStreamCreateWithFlags(&g_s2, cudaStreamNonBlocking);
        cudaEventCreateWithFlags(&g_ev0,    cudaEventDisableTiming);
        cudaEventCreateWithFlags(&g_evFin,  cudaEventDisableTiming);
        cudaEventCreateWithFlags(&g_evScat, cudaEventDisableTiming);
        cudaGetSymbolAddress(&g_cnt_addr, g_cnt);
    }
} g_streamInit;
}

// ---------------- grid barrier (single-wave, monotonic counter) --------------
__device__ __forceinline__ void gridbar(unsigned& phase) {
    __syncthreads();
    if (threadIdx.x == 0) {
        __threadfence();
        atomicAdd(&g_cnt, 1u);
        unsigned target = (++phase) * gridDim.x;
        while (atomicAdd(&g_cnt, 0u) < target) __nanosleep(64);
        __threadfence();
    }
    __syncthreads();
}

// ------- prep_build: zero+hist+scan+finalize (dinv/ptr/cur ready) ------------
__global__ void __launch_bounds__(1024)
prep_build_kernel(const int* __restrict__ col) {
    __shared__ int s[1024];
    __shared__ int sb[PREP_BLOCKS];
    int tid = threadIdx.x, bid = blockIdx.x;
    int i = bid * 1024 + tid;
    unsigned phase = 0;

    d_cnt[i] = 0;
    gridbar(phase);

    #pragma unroll
    for (int j = 0; j < EE / NN; j++)
        atomicAdd(&d_cnt[col[i + j * NN]], 1);
    gridbar(phase);

    int v = d_cnt[i];
    s[tid] = v;
    __syncthreads();
    #pragma unroll
    for (int off = 1; off < 1024; off <<= 1) {
        int t = (tid >= off) ? s[tid - off] : 0;
        __syncthreads();
        s[tid] += t;
        __syncthreads();
    }
    int le = s[tid] - v;
    if (tid == 1023) d_bsum[bid] = s[1023];
    gridbar(phase);

    if (tid < PREP_BLOCKS) sb[tid] = d_bsum[tid];
    __syncthreads();
    #pragma unroll
    for (int off = 1; off < PREP_BLOCKS; off <<= 1) {
        int t = (tid < PREP_BLOCKS && tid >= off) ? sb[tid - off] : 0;
        __syncthreads();
        if (tid < PREP_BLOCKS) sb[tid] += t;
        __syncthreads();
    }
    int bex = (bid == 0) ? 0 : sb[bid - 1];

    int p = le + bex;
    d_ptr[i] = p;
    d_cur[i] = p;
    d_dinv[i] = rsqrtf((float)v + 1.0f);
}

// ------- scatter: CSR row fill (plain kernel, overlaps conv2) ----------------
__global__ void scatter_kernel(const int* __restrict__ row, const int* __restrict__ col) {
    int e = blockIdx.x * blockDim.x + threadIdx.x;
    int c = col[e];
    int q = atomicAdd(&d_cur[c], 1);
    d_srow[q] = row[e];
}

// ---------------- conv1: (B,T,9) -> relu -> pool2 -> d_h1 [b][c][t] ----------
__global__ void conv1_kernel(const float* __restrict__ x,
                             const float* __restrict__ w,
                             const float* __restrict__ bias) {
    __shared__ __align__(16) float xs[TW * 9];
    __shared__ __align__(16) float ws[720];
    __shared__ float bs[16];
    int b = blockIdx.y, tp0 = blockIdx.x * 128, tid = threadIdx.x;

    for (int j = tid; j < 720; j += 128) {
        int c = j & 15, r = j >> 4, f = r / 5, k = r - f * 5;
        ws[j] = w[c * 45 + f * 5 + k];
    }
    if (tid < 16) bs[tid] = bias[tid];

    int base = 2 * tp0 - 2;
    const float* xb = x + (size_t)b * TT * FIN;
    for (int j = tid; j < TW * 9; j += 128) {
        int t = base + j / 9, f = j - (j / 9) * 9;
        xs[j] = (t >= 0 && t < TT) ? xb[t * 9 + f] : 0.0f;
    }
    __syncthreads();

    float s0[16], s1[16];
    #pragma unroll
    for (int c = 0; c < 16; c++) { s0[c] = 0.f; s1[c] = 0.f; }

    #pragma unroll
    for (int f = 0; f < 9; f++) {
        float v[6];
        #pragma unroll
        for (int j = 0; j < 6; j++) v[j] = xs[(2 * tid + j) * 9 + f];
        #pragma unroll
        for (int k = 0; k < 5; k++) {
            const float4* wr = (const float4*)&ws[(f * 5 + k) * 16];
            float a = v[k], bb = v[k + 1];
            #pragma unroll
            for (int q = 0; q < 4; q++) {
                float4 w4 = wr[q];
                s0[q*4+0] += w4.x * a;  s1[q*4+0] += w4.x * bb;
                s0[q*4+1] += w4.y * a;  s1[q*4+1] += w4.y * bb;
                s0[q*4+2] += w4.z * a;  s1[q*4+2] += w4.z * bb;
                s0[q*4+3] += w4.w * a;  s1[q*4+3] += w4.w * bb;
            }
        }
    }

    float* hb = d_h1 + (size_t)b * 16 * T1 + tp0 + tid;
    #pragma unroll
    for (int c = 0; c < 16; c++)
        hb[c * T1] = fmaxf(fmaxf(s0[c], s1[c]) + bs[c], 0.f);
}

// ------- conv2 (8pos x 4ch tile): d_h1 [b][c][t] -> g16 = fp16(dinv*h2) -----
__global__ void __launch_bounds__(256)
conv2_kernel(const float* __restrict__ w2, const float* __restrict__ b2) {
    __shared__ __align__(16) float buf[16 * TW];
    __shared__ __align__(16) float ws[2560];        // [(ci*5+k)*32 + c]
    __shared__ float bs[32];
    int b = blockIdx.y, tid = threadIdx.x;
    int cg = tid & 7, pg = tid >> 3;                // 8 ch-groups x 32 pos-groups
    int t0 = blockIdx.x * 256;

    for (int j = tid; j < 2560; j += 256) {
        int c = j & 31, r = j >> 5;
        ws[j] = w2[c * 80 + r];
    }
    if (tid < 32) bs[tid] = b2[tid];

    int base = t0 - 2;
    const float* hb = d_h1 + (size_t)b * 16 * T1;
    #pragma unroll
    for (int ci = 0; ci < 16; ci++)
        for (int j = tid; j < TW; j += 256) {
            int t = base + j;
            buf[ci * TW + j] = (t >= 0 && t < T1) ? hb[ci * T1 + t] : 0.f;
        }
    __syncthreads();

    float acc[32];                                  // [p 0..7][cc 0..3]
    #pragma unroll
    for (int o = 0; o < 32; o++) acc[o] = 0.f;

    #pragma unroll 4
    for (int ci = 0; ci < 16; ci++) {
        float v[12];
        const float4* vp = (const float4*)(buf + ci * TW + pg * 8);
        #pragma unroll
        for (int q = 0; q < 3; q++) {
            float4 t4 = vp[q];
            v[q*4+0] = t4.x; v[q*4+1] = t4.y; v[q*4+2] = t4.z; v[q*4+3] = t4.w;
        }
        #pragma unroll
        for (int k = 0; k < 5; k++) {
            float4 w4 = *(const float4*)&ws[(ci * 5 + k) * 32 + cg * 4];
            #pragma unroll
            for (int p = 0; p < 8; p++) {
                float a = v[p + k];
                acc[p*4+0] += a * w4.x;
                acc[p*4+1] += a * w4.y;
                acc[p*4+2] += a * w4.z;
                acc[p*4+3] += a * w4.w;
            }
        }
    }

    int nbase = b * TPP + (t0 >> 1) + pg * 4;
    #pragma unroll
    for (int pp = 0; pp < 4; pp++) {
        int n = nbase + pp;
        float dv = d_dinv[n];
        int pa = pp * 8, pb = pa + 4;
        float c0 = fmaxf(fmaxf(acc[pa+0], acc[pb+0]) + bs[cg*4+0], 0.f) * dv;
        float c1 = fmaxf(fmaxf(acc[pa+1], acc[pb+1]) + bs[cg*4+1], 0.f) * dv;
        float c2 = fmaxf(fmaxf(acc[pa+2], acc[pb+2]) + bs[cg*4+2], 0.f) * dv;
        float c3 = fmaxf(fmaxf(acc[pa+3], acc[pb+3]) + bs[cg*4+3], 0.f) * dv;
        __half2* o = (__half2*)(d_g16 + (size_t)n * 32 + cg * 4);
        o[0] = __floats2half2_rn(c0, c1);
        o[1] = __floats2half2_rn(c2, c3);
    }
}

// ------- fused layer 1: 8 nodes/warp (octet each) + GEMM 32->64 -------------
// Row = 32ch fp16 = 64B = 4 lanes x uint4 (8 ch each).
__global__ void gcn1_fused_kernel(const float* __restrict__ w,
                                  const float* __restrict__ bias) {
    __shared__ __align__(16) float ws[2048];     // W1 [c][o], 32x64
    __shared__ float bs[64];
    __shared__ __align__(16) float st[8][256];   // per-warp: 8 nodes x 32 ch
    int tid = threadIdx.x;
    for (int j = tid; j < 2048; j += 256) ws[j] = w[j];
    if (tid < 64) bs[tid] = bias[tid];
    __syncthreads();

    int warp = tid >> 5, lane = tid & 31;
    int oct = lane >> 2, ol = lane & 3;          // octet id 0..7, lane-in-octet 0..3
    int nbase = (blockIdx.x * 8 + warp) * 8;
    int n = nbase + oct;
    int p = d_ptr[n];
    int cnt = d_cnt[n];
    const uint4* gp = (const uint4*)d_g16 + ol;  // +r*4 selects row r (64B rows)

    // self loop (lane covers channels 8*ol .. 8*ol+7)
    float a[8];
    {
        uint4 v = gp[n << 2];
        const __half2* h = (const __half2*)&v;
        #pragma unroll
        for (int j = 0; j < 4; j++) {
            float2 f = __half22float2(h[j]);
            a[2*j] = f.x; a[2*j+1] = f.y;
        }
    }

    int e = 0;
    for (; e + 2 <= cnt; e += 2) {
        int r0 = d_srow[p+e], r1 = d_srow[p+e+1];
        uint4 v0 = gp[r0 << 2];
        uint4 v1 = gp[r1 << 2];
        const __half2* h0 = (const __half2*)&v0;
        const __half2* h1 = (const __half2*)&v1;
        #pragma unroll
        for (int j = 0; j < 4; j++) {
            float2 f0 = __half22float2(h0[j]);
            float2 f1 = __half22float2(h1[j]);
            a[2*j]   += f0.x + f1.x;
            a[2*j+1] += f0.y + f1.y;
        }
    }
    for (; e < cnt; e++) {
        int r = d_srow[p + e];
        uint4 v = gp[r << 2];
        const __half2* h = (const __half2*)&v;
        #pragma unroll
        for (int j = 0; j < 4; j++) {
            float2 f = __half22float2(h[j]);
            a[2*j] += f.x; a[2*j+1] += f.y;
        }
    }

    *(float4*)&st[warp][oct * 32 + 8 * ol]     = make_float4(a[0], a[1], a[2], a[3]);
    *(float4*)&st[warp][oct * 32 + 8 * ol + 4] = make_float4(a[4], a[5], a[6], a[7]);
    __syncwarp();

    // epilogue: 8 nodes, full warp; lane -> channels 2*lane, 2*lane+1
    #pragma unroll
    for (int k = 0; k < 8; k++) {
        int nk = nbase + k;
        float s0 = 0.f, s1 = 0.f;
        #pragma unroll
        for (int c = 0; c < 32; c++) {
            float v = st[warp][k * 32 + c];
            float2 wp = ((const float2*)&ws[c * 64])[lane];
            s0 += v * wp.x;
            s1 += v * wp.y;
        }
        float dv = d_dinv[nk];
        float o0 = fmaxf(dv * s0 + bs[2 * lane],     0.f) * dv;
        float o1 = fmaxf(dv * s1 + bs[2 * lane + 1], 0.f) * dv;
        ((__half2*)d_gB16)[(nk << 5) + lane] = __floats2half2_rn(o0, o1);
    }
}

// ---------------- init out = fcb (per replay, before atomics) ----------------
__global__ void init_out_kernel(const float* __restrict__ fcb, float* __restrict__ out) {
    out[blockIdx.x * 6 + threadIdx.x] = fcb[threadIdx.x];
}

// ------- fused layer 2 + pool + FC: 4 nodes/warp + GEMM + pooled FC ---------
// Row = 64ch fp16 = 128B = 8 lanes x uint4 (8 ch each).
// Block = 32 consecutive nodes (batch b = blockIdx.x >> 4).
__global__ void gcn2_pool_kernel(const float* __restrict__ w,
                                 const float* __restrict__ bias,
                                 const float* __restrict__ fcw,
                                 float* __restrict__ out) {
    __shared__ __align__(16) float ws[4096];     // W2 [c][o], 64x64
    __shared__ float bs[64];
    __shared__ float fw[384];                    // fcW [o][k], 6x64
    __shared__ __align__(16) float st[8][256];   // per-warp: 4 nodes x 64 ch
    __shared__ float po[6];                      // block-level pooled partials
    int tid = threadIdx.x;
    for (int j = tid; j < 4096; j += 256) ws[j] = w[j];
    if (tid < 64) bs[tid] = bias[tid];
    else if (tid >= 64 && tid < 70) po[tid - 64] = 0.f;
    for (int j = tid; j < 384; j += 256) fw[j] = fcw[j];
    __syncthreads();

    int warp = tid >> 5, lane = tid & 31;
    int q = lane >> 3, ql = lane & 7;            // quarter id, lane-in-quarter
    int nbase = blockIdx.x * 32 + warp * 4;
    int n = nbase + q;
    int p = d_ptr[n];
    int cnt = d_cnt[n];
    const uint4* gp = (const uint4*)d_gB16 + ql; // +r*8 selects row r (128B rows)

    // self loop (lane covers channels 8*ql .. 8*ql+7)
    float a[8];
    {
        uint4 v = gp[n << 3];
        const __half2* h = (const __half2*)&v;
        #pragma unroll
        for (int j = 0; j < 4; j++) {
            float2 f = __half22float2(h[j]);
            a[2*j] = f.x; a[2*j+1] = f.y;
        }
    }

    int e = 0;
    for (; e + 2 <= cnt; e += 2) {
        int r0 = d_srow[p+e], r1 = d_srow[p+e+1];
        uint4 v0 = gp[r0 << 3];
        uint4 v1 = gp[r1 << 3];
        const __half2* h0 = (const __half2*)&v0;
        const __half2* h1 = (const __half2*)&v1;
        #pragma unroll
        for (int j = 0; j < 4; j++) {
            float2 f0 = __half22float2(h0[j]);
            float2 f1 = __half22float2(h1[j]);
            a[2*j]   += f0.x + f1.x;
            a[2*j+1] += f0.y + f1.y;
        }
    }
    for (; e < cnt; e++) {
        int r = d_srow[p + e];
        uint4 v = gp[r << 3];
        const __half2* h = (const __half2*)&v;
        #pragma unroll
        for (int j = 0; j < 4; j++) {
            float2 f = __half22float2(h[j]);
            a[2*j] += f.x; a[2*j+1] += f.y;
        }
    }

    *(float4*)&st[warp][q * 64 + 8 * ql]     = make_float4(a[0], a[1], a[2], a[3]);
    *(float4*)&st[warp][q * 64 + 8 * ql + 4] = make_float4(a[4], a[5], a[6], a[7]);
    __syncwarp();

    // epilogue: GEMM 64->64 + relu for all 4 nodes; FC partials accumulated,
    // single butterfly reduce at the end.
    float f6[6];
    #pragma unroll
    for (int o = 0; o < 6; o++) f6[o] = 0.f;

    #pragma unroll
    for (int k = 0; k < 4; k++) {
        int nk = nbase + k;
        float s0 = 0.f, s1 = 0.f;
        #pragma unroll
        for (int c = 0; c < 64; c++) {
            float v = st[warp][k * 64 + c];
            float2 wp = ((const float2*)&ws[c * 64])[lane];
            s0 += v * wp.x;
            s1 += v * wp.y;
        }
        float dv = d_dinv[nk];
        float h0 = fmaxf(dv * s0 + bs[2 * lane],     0.f);
        float h1 = fmaxf(dv * s1 + bs[2 * lane + 1], 0.f);

        #pragma unroll
        for (int o = 0; o < 6; o++)
            f6[o] += h0 * fw[o * 64 + 2 * lane] + h1 * fw[o * 64 + 2 * lane + 1];
    }

    #pragma unroll
    for (int o = 0; o < 6; o++) {
        float c6 = f6[o];
        c6 += __shfl_xor_sync(0xffffffffu, c6, 1);
        c6 += __shfl_xor_sync(0xffffffffu, c6, 2);
        c6 += __shfl_xor_sync(0xffffffffu, c6, 4);
        c6 += __shfl_xor_sync(0xffffffffu, c6, 8);
        c6 += __shfl_xor_sync(0xffffffffu, c6, 16);
        if (lane == 0) atomicAdd(&po[o], c6);
    }

    __syncthreads();
    if (tid < 6)
        atomicAdd(&out[(blockIdx.x >> 4) * 6 + tid], po[tid] * (1.0f / TPP));
}

// ---------------- launch -----------------------------------------------------
extern "C" void kernel_launch(void* const* d_in, const int* in_sizes, int n_in,
                              void* d_out, int out_size) {
    const float* x   = (const float*)d_in[0];
    const int*   ei  = (const int*)  d_in[1];
    const float* w1  = (const float*)d_in[2];
    const float* b1  = (const float*)d_in[3];
    const float* w2  = (const float*)d_in[4];
    const float* b2  = (const float*)d_in[5];
    const float* g1w = (const float*)d_in[6];
    const float* g1b = (const float*)d_in[7];
    const float* g2w = (const float*)d_in[8];
    const float* g2b = (const float*)d_in[9];
    const float* fcw = (const float*)d_in[10];
    const float* fcb = (const float*)d_in[11];
    float* out = (float*)d_out;

    // fork: prep_build then scatter on side stream
    cudaEventRecord(g_ev0, 0);
    cudaStreamWaitEvent(g_s2, g_ev0, 0);
    cudaMemsetAsync(g_cnt_addr, 0, sizeof(unsigned), g_s2);
    prep_build_kernel<<<PREP_BLOCKS, 1024, 0, g_s2>>>(ei + EE);
    cudaEventRecord(g_evFin, g_s2);
    scatter_kernel<<<EE / 256, 256, 0, g_s2>>>(ei, ei + EE);
    cudaEventRecord(g_evScat, g_s2);

    // main stream: conv1 overlaps prep_build; conv2 overlaps scatter
    conv1_kernel<<<dim3(8, BB), 128>>>(x, w1, b1);
    init_out_kernel<<<BB, 6>>>(fcb, out);
    cudaStreamWaitEvent(0, g_evFin, 0);           // conv2 needs dinv only
    conv2_kernel<<<dim3(4, BB), 256>>>(w2, b2);
    cudaStreamWaitEvent(0, g_evScat, 0);          // gathers need CSR

    // fused GCN layers
    gcn1_fused_kernel<<<NN / 64, 256>>>(g1w, g1b);       // 8 nodes/warp
    gcn2_pool_kernel<<<NN / 32, 256>>>(g2w, g2b, fcw, out);  // 4 nodes/warp + pooled FC
}